// round 1
// baseline (speedup 1.0000x reference)
#include <cuda_runtime.h>
#include <cstdint>

#define BB   2
#define NN   8192
#define CIN  64
#define CCAT 67
#define KK   16
#define H1   32
#define H2   64
#define COUT 64

__device__ int g_knn[BB * NN * KK];

// ---------------------------------------------------------------------------
// KNN: brute force, stable top-16 by (d2, index) ascending.
// 32 queries/block x 8 candidate slices = 256 threads.
// ---------------------------------------------------------------------------
#define QPB  32
#define SLC  8
#define TILE 512

__global__ __launch_bounds__(256) void knn_kernel(const float* __restrict__ coords) {
    __shared__ float4 s_cand[TILE];
    __shared__ float  s_d[QPB * KK * SLC];
    __shared__ int    s_i[QPB * KK * SLC];

    const int b     = blockIdx.y;
    const int ql    = threadIdx.x >> 3;
    const int slice = threadIdx.x & 7;
    const int q     = blockIdx.x * QPB + ql;
    const float* cb = coords + (size_t)b * NN * 3;

    const float qx = cb[q * 3 + 0], qy = cb[q * 3 + 1], qz = cb[q * 3 + 2];
    const float qsq = fmaf(qz, qz, fmaf(qy, qy, qx * qx));

    float dist[KK];
    int   idx[KK];
#pragma unroll
    for (int j = 0; j < KK; j++) { dist[j] = 3.4e38f; idx[j] = 0x7fffffff; }

    for (int t = 0; t < NN; t += TILE) {
        __syncthreads();
        for (int i = threadIdx.x; i < TILE; i += QPB * SLC) {
            const int m = t + i;
            float x = cb[m * 3 + 0], y = cb[m * 3 + 1], z = cb[m * 3 + 2];
            s_cand[i] = make_float4(x, y, z, fmaf(z, z, fmaf(y, y, x * x)));
        }
        __syncthreads();
#pragma unroll 4
        for (int i = slice; i < TILE; i += SLC) {
            const float4 c = s_cand[i];
            const float dot = fmaf(qz, c.z, fmaf(qy, c.y, qx * c.x));
            const float d = (qsq + c.w) - 2.0f * dot;
            if (d < dist[KK - 1]) {
                // stable insertion: strict < on entry, then carry-shift
                float dd = d; int mm = t + i;
                bool carry = false;
#pragma unroll
                for (int j = 0; j < KK; j++) {
                    const bool sw = carry || (dd < dist[j]);
                    if (sw) {
                        const float td = dist[j]; const int ti = idx[j];
                        dist[j] = dd; idx[j] = mm;
                        dd = td; mm = ti;
                        carry = true;
                    }
                }
            }
        }
    }

    const int base = ql * (KK * SLC) + slice * KK;
#pragma unroll
    for (int j = 0; j < KK; j++) { s_d[base + j] = dist[j]; s_i[base + j] = idx[j]; }
    __syncwarp();

    if (slice == 0) {
        int head[SLC];
#pragma unroll
        for (int s = 0; s < SLC; s++) head[s] = 0;
        int* outp = g_knn + ((size_t)b * NN + q) * KK;
        const int qb = ql * (KK * SLC);
        for (int r = 0; r < KK; r++) {
            float bd = 3.5e38f; int bi = 0x7fffffff; int bs = 0;
#pragma unroll
            for (int s = 0; s < SLC; s++) {
                const int h = head[s];
                const float dv = s_d[qb + s * KK + h];
                const int   iv = s_i[qb + s * KK + h];
                if (dv < bd || (dv == bd && iv < bi)) { bd = dv; bi = iv; bs = s; }
            }
#pragma unroll
            for (int s = 0; s < SLC; s++) if (s == bs) head[s]++;
            outp[r] = bi;
        }
    }
}

// ---------------------------------------------------------------------------
// Fused gather + 3-layer MLP + (sum, max-pool, attentive-aggr).
// One warp per point, 8 points per 256-thread block.
// All hot shared loads are LDS.128 with conflict-free padded strides.
// ---------------------------------------------------------------------------
#define FMA4(acc, v, wv)                         \
    acc = fmaf((v).x, (wv).x, acc);              \
    acc = fmaf((v).y, (wv).y, acc);              \
    acc = fmaf((v).z, (wv).z, acc);              \
    acc = fmaf((v).w, (wv).w, acc)

#define LD4(p) (*reinterpret_cast<const float4*>(p))
#define ST4(p) (*reinterpret_cast<float4*>(p))

__global__ __launch_bounds__(256) void mlp_kernel(
    const float* __restrict__ pf, const float* __restrict__ coords,
    const float* __restrict__ w1, const float* __restrict__ b1,
    const float* __restrict__ w2, const float* __restrict__ b2,
    const float* __restrict__ w3, const float* __restrict__ b3,
    const float* __restrict__ aggr_w, const float* __restrict__ aggr_b,
    float* __restrict__ out)
{
    extern __shared__ float sm[];
    float* s_w1 = sm;                 // 32*68  = 2176
    float* s_w2 = s_w1 + 32 * 68;     // 64*36  = 2304
    float* s_w3 = s_w2 + 64 * 36;     // 64*68  = 4352
    float* s_b1 = s_w3 + 64 * 68;     // 32
    float* s_b2 = s_b1 + 32;          // 64
    float* s_b3 = s_b2 + 64;          // 64
    float* s_aw = s_b3 + 64;          // 16
    float* s_g  = s_aw + 16;          // 8 * 1088
    float* s_h1 = s_g + 8 * 1088;     // 8 * 512

    const int tid  = threadIdx.x;
    const int lane = tid & 31;
    const int w    = tid >> 5;

    for (int i = tid; i < H1 * CCAT; i += 256) { int o = i / 67, c = i % 67; s_w1[o * 68 + c] = w1[i]; }
    for (int i = tid; i < H2 * H1;   i += 256) { int o = i >> 5, c = i & 31; s_w2[o * 36 + c] = w2[i]; }
    for (int i = tid; i < COUT * H2; i += 256) { int o = i >> 6, c = i & 63; s_w3[o * 68 + c] = w3[i]; }
    if (tid < 32) s_b1[tid] = b1[tid];
    if (tid >= 32 && tid < 96) s_b2[tid - 32] = b2[tid - 32];
    if (tid >= 96 && tid < 160) s_b3[tid - 96] = b3[tid - 96];
    if (tid >= 160 && tid < 176) s_aw[tid - 160] = aggr_w[tid - 160];
    __syncthreads();

    const int gp = blockIdx.x * 8 + w;
    const int b  = gp >> 13;
    const float* pfb = pf + (size_t)b * NN * CIN;
    const float* cob = coords + (size_t)b * NN * 3;
    const int* kn = g_knn + (size_t)gp * KK;
    float* s_gp  = s_g  + w * 1088;
    float* s_h1p = s_h1 + w * 512;

    const int nk = kn[lane & 15];

    // gather neighbor features (2 neighbors per pass, float4 per lane)
#pragma unroll
    for (int k2 = 0; k2 < KK; k2 += 2) {
        const int k = k2 + (lane >> 4);
        const int m = __shfl_sync(0xffffffffu, nk, k);
        const int cc = (lane & 15) * 4;
        const float4 v = LD4(pfb + (size_t)m * CIN + cc);
        ST4(s_gp + k * 68 + cc) = v;
    }
    // gather neighbor coords
    if (lane < KK) {
        const float* cp = cob + (size_t)nk * 3;
        s_gp[lane * 68 + 64] = cp[0];
        s_gp[lane * 68 + 65] = cp[1];
        s_gp[lane * 68 + 66] = cp[2];
    }
    __syncwarp();
    // relative coords vs neighbor slot 0 (self)
    if (lane < 3) {
        const float c0 = s_gp[64 + lane];
#pragma unroll
        for (int k = 0; k < KK; k++) s_gp[k * 68 + 64 + lane] -= c0;
    }
    __syncwarp();

    float* op = out + (size_t)gp * 192;

    // max-pool over k of raw features -> out[64..127]
    {
        const int cc = (lane & 15) * 4;
        const int k0 = (lane >> 4) * 8;
        float4 p = LD4(s_gp + k0 * 68 + cc);
#pragma unroll
        for (int k = 1; k < 8; k++) {
            const float4 v = LD4(s_gp + (k0 + k) * 68 + cc);
            p.x = fmaxf(p.x, v.x); p.y = fmaxf(p.y, v.y);
            p.z = fmaxf(p.z, v.z); p.w = fmaxf(p.w, v.w);
        }
        p.x = fmaxf(p.x, __shfl_xor_sync(0xffffffffu, p.x, 16));
        p.y = fmaxf(p.y, __shfl_xor_sync(0xffffffffu, p.y, 16));
        p.z = fmaxf(p.z, __shfl_xor_sync(0xffffffffu, p.z, 16));
        p.w = fmaxf(p.w, __shfl_xor_sync(0xffffffffu, p.w, 16));
        if (lane < 16) ST4(op + 64 + cc) = p;
    }

    // ----- layer 1: h1[k][o] = b1[o] + sum_c g[k][c] * w1[o][c], o = lane -----
#pragma unroll 1
    for (int kb = 0; kb < 4; kb++) {
        const float* gr = s_gp + kb * 4 * 68;
        float a0 = s_b1[lane], a1 = a0, a2 = a0, a3 = a0;
#pragma unroll
        for (int c = 0; c < 64; c += 4) {
            const float4 wv = LD4(s_w1 + lane * 68 + c);
            const float4 g0 = LD4(gr + c);
            const float4 g1 = LD4(gr + 68 + c);
            const float4 g2 = LD4(gr + 136 + c);
            const float4 g3 = LD4(gr + 204 + c);
            FMA4(a0, g0, wv); FMA4(a1, g1, wv); FMA4(a2, g2, wv); FMA4(a3, g3, wv);
        }
#pragma unroll
        for (int c = 64; c < 67; c++) {
            const float wv = s_w1[lane * 68 + c];
            a0 = fmaf(gr[c], wv, a0);
            a1 = fmaf(gr[68 + c], wv, a1);
            a2 = fmaf(gr[136 + c], wv, a2);
            a3 = fmaf(gr[204 + c], wv, a3);
        }
        s_h1p[(kb * 4 + 0) * 32 + lane] = a0;
        s_h1p[(kb * 4 + 1) * 32 + lane] = a1;
        s_h1p[(kb * 4 + 2) * 32 + lane] = a2;
        s_h1p[(kb * 4 + 3) * 32 + lane] = a3;
    }
    __syncwarp();

    // ----- layer 2: h2[k][o] (o = lane, lane+32), h2 overlays s_gp -----
#pragma unroll 1
    for (int kb = 0; kb < 4; kb++) {
        const float* hr = s_h1p + kb * 4 * 32;
        float aA0 = s_b2[lane],      aA1 = aA0, aA2 = aA0, aA3 = aA0;
        float aB0 = s_b2[lane + 32], aB1 = aB0, aB2 = aB0, aB3 = aB0;
#pragma unroll
        for (int c = 0; c < 32; c += 4) {
            const float4 wA = LD4(s_w2 + lane * 36 + c);
            const float4 wB = LD4(s_w2 + (lane + 32) * 36 + c);
            const float4 v0 = LD4(hr + c);
            const float4 v1 = LD4(hr + 32 + c);
            const float4 v2 = LD4(hr + 64 + c);
            const float4 v3 = LD4(hr + 96 + c);
            FMA4(aA0, v0, wA); FMA4(aA1, v1, wA); FMA4(aA2, v2, wA); FMA4(aA3, v3, wA);
            FMA4(aB0, v0, wB); FMA4(aB1, v1, wB); FMA4(aB2, v2, wB); FMA4(aB3, v3, wB);
        }
        s_gp[(kb * 4 + 0) * 68 + lane] = aA0; s_gp[(kb * 4 + 0) * 68 + 32 + lane] = aB0;
        s_gp[(kb * 4 + 1) * 68 + lane] = aA1; s_gp[(kb * 4 + 1) * 68 + 32 + lane] = aB1;
        s_gp[(kb * 4 + 2) * 68 + lane] = aA2; s_gp[(kb * 4 + 2) * 68 + 32 + lane] = aB2;
        s_gp[(kb * 4 + 3) * 68 + lane] = aA3; s_gp[(kb * 4 + 3) * 68 + 32 + lane] = aB3;
    }
    __syncwarp();

    // ----- layer 3 + reductions -----
    float sum0 = 0.f, sum1 = 0.f, ag0 = 0.f, ag1 = 0.f;
#pragma unroll 1
    for (int kb = 0; kb < 4; kb++) {
        const float* hr = s_gp + kb * 4 * 68;
        float aA0 = s_b3[lane],      aA1 = aA0, aA2 = aA0, aA3 = aA0;
        float aB0 = s_b3[lane + 32], aB1 = aB0, aB2 = aB0, aB3 = aB0;
#pragma unroll
        for (int c = 0; c < 64; c += 4) {
            const float4 wA = LD4(s_w3 + lane * 68 + c);
            const float4 wB = LD4(s_w3 + (lane + 32) * 68 + c);
            const float4 v0 = LD4(hr + c);
            const float4 v1 = LD4(hr + 68 + c);
            const float4 v2 = LD4(hr + 136 + c);
            const float4 v3 = LD4(hr + 204 + c);
            FMA4(aA0, v0, wA); FMA4(aA1, v1, wA); FMA4(aA2, v2, wA); FMA4(aA3, v3, wA);
            FMA4(aB0, v0, wB); FMA4(aB1, v1, wB); FMA4(aB2, v2, wB); FMA4(aB3, v3, wB);
        }
        const float u0 = s_aw[kb * 4 + 0], u1 = s_aw[kb * 4 + 1];
        const float u2 = s_aw[kb * 4 + 2], u3 = s_aw[kb * 4 + 3];
        sum0 += (aA0 + aA1) + (aA2 + aA3);
        sum1 += (aB0 + aB1) + (aB2 + aB3);
        ag0 = fmaf(u0, aA0, fmaf(u1, aA1, fmaf(u2, aA2, fmaf(u3, aA3, ag0))));
        ag1 = fmaf(u0, aB0, fmaf(u1, aB1, fmaf(u2, aB2, fmaf(u3, aB3, ag1))));
    }
    const float ab = aggr_b[0];
    op[lane]       = sum0;
    op[32 + lane]  = sum1;
    op[128 + lane] = ag0 + ab;
    op[160 + lane] = ag1 + ab;
}

// ---------------------------------------------------------------------------
extern "C" void kernel_launch(void* const* d_in, const int* in_sizes, int n_in,
                              void* d_out, int out_size) {
    const float* pf     = (const float*)d_in[0];
    const float* coords = (const float*)d_in[1];
    const float* w1     = (const float*)d_in[2];
    const float* b1     = (const float*)d_in[3];
    const float* w2     = (const float*)d_in[4];
    const float* b2     = (const float*)d_in[5];
    const float* w3     = (const float*)d_in[6];
    const float* b3     = (const float*)d_in[7];
    const float* aw     = (const float*)d_in[8];
    const float* ab     = (const float*)d_in[9];
    float* out = (float*)d_out;

    dim3 kgrid(NN / QPB, BB);
    knn_kernel<<<kgrid, 256>>>(coords);

    const int smem = (32 * 68 + 64 * 36 + 64 * 68 + 32 + 64 + 64 + 16 +
                      8 * 1088 + 8 * 512) * (int)sizeof(float);
    cudaFuncSetAttribute(mlp_kernel, cudaFuncAttributeMaxDynamicSharedMemorySize, smem);
    mlp_kernel<<<(BB * NN) / 8, 256, smem>>>(pf, coords, w1, b1, w2, b2, w3, b3, aw, ab, out);
}

// round 2
// speedup vs baseline: 1.7168x; 1.7168x over previous
#include <cuda_runtime.h>
#include <cstdint>

#define BB   2
#define NN   8192
#define CIN  64
#define CCAT 67
#define KK   16
#define H1   32
#define H2   64
#define COUT 64

#define GRID 8            // 8x8x8 cells
#define NCELL (GRID*GRID*GRID)
#define CS   0.125f       // cell size

__device__ int    g_knn[BB * NN * KK];
__device__ int    g_cnt[BB * NCELL];
__device__ int    g_cur[BB * NCELL];
__device__ int    g_start[BB * (NCELL + 1)];
__device__ float4 g_sorted[BB * NN];

__device__ __forceinline__ int cell_of(float x, float y, float z) {
    int ix = min(GRID - 1, max(0, (int)(x * (float)GRID)));
    int iy = min(GRID - 1, max(0, (int)(y * (float)GRID)));
    int iz = min(GRID - 1, max(0, (int)(z * (float)GRID)));
    return (iz * GRID + iy) * GRID + ix;
}

// ---------------------------------------------------------------------------
__global__ void knn_zero() {
    int t = threadIdx.x;
    if (t < BB * NCELL) g_cnt[t] = 0;
}

__global__ void knn_bin(const float* __restrict__ coords) {
    int t = blockIdx.x * blockDim.x + threadIdx.x;
    int b = t >> 13, q = t & (NN - 1);
    const float* cp = coords + ((size_t)b * NN + q) * 3;
    int c = cell_of(cp[0], cp[1], cp[2]);
    atomicAdd(&g_cnt[b * NCELL + c], 1);
}

__global__ void knn_scan() {
    __shared__ int s[NCELL];
    const int b = blockIdx.x, t = threadIdx.x;
    const int my = g_cnt[b * NCELL + t];
    s[t] = my;
    __syncthreads();
    for (int off = 1; off < NCELL; off <<= 1) {
        int v = (t >= off) ? s[t - off] : 0;
        __syncthreads();
        s[t] += v;
        __syncthreads();
    }
    g_start[b * (NCELL + 1) + t + 1] = s[t];
    if (t == 0) g_start[b * (NCELL + 1)] = 0;
    g_cur[b * NCELL + t] = s[t] - my;   // exclusive prefix = write cursor
}

__global__ void knn_scatter(const float* __restrict__ coords) {
    int t = blockIdx.x * blockDim.x + threadIdx.x;
    int b = t >> 13, q = t & (NN - 1);
    const float* cp = coords + ((size_t)b * NN + q) * 3;
    float x = cp[0], y = cp[1], z = cp[2];
    int c = cell_of(x, y, z);
    int pos = atomicAdd(&g_cur[b * NCELL + c], 1);
    g_sorted[(size_t)b * NN + pos] = make_float4(x, y, z, __int_as_float(q));
}

// ---------------------------------------------------------------------------
// Exact KNN via expanding Chebyshev rings. Thread per query.
// Top-16 kept as packed u64 keys (sortable(d)<<32 | idx) -> exact stable
// (d, idx) ascending order, matching jax.lax.top_k tie-breaking.
// ---------------------------------------------------------------------------
__global__ __launch_bounds__(64) void knn_main(const float* __restrict__ coords) {
    const int t = blockIdx.x * 64 + threadIdx.x;
    const int b = t >> 13, q = t & (NN - 1);
    const float* cp = coords + ((size_t)b * NN + q) * 3;
    const float qx = cp[0], qy = cp[1], qz = cp[2];
    const float qsq = fmaf(qz, qz, fmaf(qy, qy, qx * qx));
    const int cx = min(GRID - 1, max(0, (int)(qx * (float)GRID)));
    const int cy = min(GRID - 1, max(0, (int)(qy * (float)GRID)));
    const int cz = min(GRID - 1, max(0, (int)(qz * (float)GRID)));

    unsigned long long keys[KK];
#pragma unroll
    for (int j = 0; j < KK; j++) keys[j] = 0xFF80000000000000ull;  // d=+inf
    float thr = __int_as_float(0x7F800000);  // +inf

    const float4* sp = g_sorted + (size_t)b * NN;
    const int* st = g_start + b * (NCELL + 1);

    for (int R = 0; R <= GRID - 1; ++R) {
        const int z0 = max(cz - R, 0), z1 = min(cz + R, GRID - 1);
        const int y0 = max(cy - R, 0), y1 = min(cy + R, GRID - 1);
        const int x0 = max(cx - R, 0), x1 = min(cx + R, GRID - 1);
        for (int z = z0; z <= z1; z++) {
            const int az = abs(z - cz);
            for (int y = y0; y <= y1; y++) {
                const int ay = max(az, abs(y - cy));
                for (int x = x0; x <= x1; x++) {
                    const int ch = max(ay, abs(x - cx));
                    if (ch != R) continue;   // ring only
                    const int c = (z * GRID + y) * GRID + x;
                    const int p1 = st[c + 1];
                    for (int p = st[c]; p < p1; ++p) {
                        const float4 cd = sp[p];
                        const float csq = fmaf(cd.z, cd.z, fmaf(cd.y, cd.y, cd.x * cd.x));
                        const float dot = fmaf(qz, cd.z, fmaf(qy, cd.y, qx * cd.x));
                        const float d = fmaf(-2.0f, dot, qsq + csq);
                        if (d < thr) {
                            unsigned s = __float_as_uint(d);
                            s ^= (unsigned)((int)s >> 31) | 0x80000000u;
                            unsigned long long k =
                                ((unsigned long long)s << 32) | (unsigned)__float_as_int(cd.w);
#pragma unroll
                            for (int j = 0; j < KK; j++) {   // branchless sorted insert
                                const unsigned long long kj = keys[j];
                                const bool cl = k < kj;
                                keys[j] = cl ? k : kj;
                                k = cl ? kj : k;
                            }
                            const unsigned hs = (unsigned)(keys[KK - 1] >> 32);
                            const unsigned ob = (hs & 0x80000000u) ? (hs ^ 0x80000000u) : ~hs;
                            thr = __uint_as_float(ob);
                        }
                    }
                }
            }
        }
        const float bound = (float)R * CS;
        if (thr < bound * bound * 0.9999f) break;  // all unscanned cells >= R*CS away
    }

    int* outp = g_knn + (size_t)t * KK;
#pragma unroll
    for (int j = 0; j < KK; j++) outp[j] = (int)(keys[j] & 0xFFFFFFFFu);
}

// ---------------------------------------------------------------------------
// Fused gather + 3-layer MLP + (sum, max-pool, attentive-aggr).
// One warp per point, 8 points per 256-thread block, 2 blocks/SM.
// ---------------------------------------------------------------------------
#define FMA4(acc, v, wv)                         \
    acc = fmaf((v).x, (wv).x, acc);              \
    acc = fmaf((v).y, (wv).y, acc);              \
    acc = fmaf((v).z, (wv).z, acc);              \
    acc = fmaf((v).w, (wv).w, acc)

#define LD4(p) (*reinterpret_cast<const float4*>(p))
#define ST4(p) (*reinterpret_cast<float4*>(p))

__global__ __launch_bounds__(256, 2) void mlp_kernel(
    const float* __restrict__ pf, const float* __restrict__ coords,
    const float* __restrict__ w1, const float* __restrict__ b1,
    const float* __restrict__ w2, const float* __restrict__ b2,
    const float* __restrict__ w3, const float* __restrict__ b3,
    const float* __restrict__ aggr_w, const float* __restrict__ aggr_b,
    float* __restrict__ out)
{
    extern __shared__ float sm[];
    float* s_w1 = sm;                 // 32*68
    float* s_w2 = s_w1 + 32 * 68;     // 64*36
    float* s_w3 = s_w2 + 64 * 36;     // 64*68
    float* s_b1 = s_w3 + 64 * 68;     // 32
    float* s_b2 = s_b1 + 32;          // 64
    float* s_b3 = s_b2 + 64;          // 64
    float* s_aw = s_b3 + 64;          // 16
    float* s_g  = s_aw + 16;          // 8 * 1088
    float* s_h1 = s_g + 8 * 1088;     // 8 * 512

    const int tid  = threadIdx.x;
    const int lane = tid & 31;
    const int w    = tid >> 5;

    for (int i = tid; i < H1 * CCAT; i += 256) { int o = i / 67, c = i % 67; s_w1[o * 68 + c] = w1[i]; }
    for (int i = tid; i < H2 * H1;   i += 256) { int o = i >> 5, c = i & 31; s_w2[o * 36 + c] = w2[i]; }
    for (int i = tid; i < COUT * H2; i += 256) { int o = i >> 6, c = i & 63; s_w3[o * 68 + c] = w3[i]; }
    if (tid < 32) s_b1[tid] = b1[tid];
    if (tid >= 32 && tid < 96) s_b2[tid - 32] = b2[tid - 32];
    if (tid >= 96 && tid < 160) s_b3[tid - 96] = b3[tid - 96];
    if (tid >= 160 && tid < 176) s_aw[tid - 160] = aggr_w[tid - 160];
    __syncthreads();

    const int gp = blockIdx.x * 8 + w;
    const int b  = gp >> 13;
    const float* pfb = pf + (size_t)b * NN * CIN;
    const float* cob = coords + (size_t)b * NN * 3;
    const int* kn = g_knn + (size_t)gp * KK;
    float* s_gp  = s_g  + w * 1088;
    float* s_h1p = s_h1 + w * 512;

    const int nk = kn[lane & 15];

#pragma unroll
    for (int k2 = 0; k2 < KK; k2 += 2) {
        const int k = k2 + (lane >> 4);
        const int m = __shfl_sync(0xffffffffu, nk, k);
        const int cc = (lane & 15) * 4;
        const float4 v = LD4(pfb + (size_t)m * CIN + cc);
        ST4(s_gp + k * 68 + cc) = v;
    }
    if (lane < KK) {
        const float* cpp = cob + (size_t)nk * 3;
        s_gp[lane * 68 + 64] = cpp[0];
        s_gp[lane * 68 + 65] = cpp[1];
        s_gp[lane * 68 + 66] = cpp[2];
    }
    __syncwarp();
    if (lane < 3) {
        const float c0 = s_gp[64 + lane];
#pragma unroll
        for (int k = 0; k < KK; k++) s_gp[k * 68 + 64 + lane] -= c0;
    }
    __syncwarp();

    float* op = out + (size_t)gp * 192;

    // max-pool over k of raw features -> out[64..127]
    {
        const int cc = (lane & 15) * 4;
        const int k0 = (lane >> 4) * 8;
        float4 p = LD4(s_gp + k0 * 68 + cc);
#pragma unroll
        for (int k = 1; k < 8; k++) {
            const float4 v = LD4(s_gp + (k0 + k) * 68 + cc);
            p.x = fmaxf(p.x, v.x); p.y = fmaxf(p.y, v.y);
            p.z = fmaxf(p.z, v.z); p.w = fmaxf(p.w, v.w);
        }
        p.x = fmaxf(p.x, __shfl_xor_sync(0xffffffffu, p.x, 16));
        p.y = fmaxf(p.y, __shfl_xor_sync(0xffffffffu, p.y, 16));
        p.z = fmaxf(p.z, __shfl_xor_sync(0xffffffffu, p.z, 16));
        p.w = fmaxf(p.w, __shfl_xor_sync(0xffffffffu, p.w, 16));
        if (lane < 16) ST4(op + 64 + cc) = p;
    }

    // ----- layer 1 -----
#pragma unroll 1
    for (int kb = 0; kb < 4; kb++) {
        const float* gr = s_gp + kb * 4 * 68;
        float a0 = s_b1[lane], a1 = a0, a2 = a0, a3 = a0;
#pragma unroll
        for (int c = 0; c < 64; c += 4) {
            const float4 wv = LD4(s_w1 + lane * 68 + c);
            const float4 g0 = LD4(gr + c);
            const float4 g1 = LD4(gr + 68 + c);
            const float4 g2 = LD4(gr + 136 + c);
            const float4 g3 = LD4(gr + 204 + c);
            FMA4(a0, g0, wv); FMA4(a1, g1, wv); FMA4(a2, g2, wv); FMA4(a3, g3, wv);
        }
#pragma unroll
        for (int c = 64; c < 67; c++) {
            const float wv = s_w1[lane * 68 + c];
            a0 = fmaf(gr[c], wv, a0);
            a1 = fmaf(gr[68 + c], wv, a1);
            a2 = fmaf(gr[136 + c], wv, a2);
            a3 = fmaf(gr[204 + c], wv, a3);
        }
        s_h1p[(kb * 4 + 0) * 32 + lane] = a0;
        s_h1p[(kb * 4 + 1) * 32 + lane] = a1;
        s_h1p[(kb * 4 + 2) * 32 + lane] = a2;
        s_h1p[(kb * 4 + 3) * 32 + lane] = a3;
    }
    __syncwarp();

    // ----- layer 2 (h2 overlays s_gp) -----
#pragma unroll 1
    for (int kb = 0; kb < 4; kb++) {
        const float* hr = s_h1p + kb * 4 * 32;
        float aA0 = s_b2[lane],      aA1 = aA0, aA2 = aA0, aA3 = aA0;
        float aB0 = s_b2[lane + 32], aB1 = aB0, aB2 = aB0, aB3 = aB0;
#pragma unroll
        for (int c = 0; c < 32; c += 4) {
            const float4 wA = LD4(s_w2 + lane * 36 + c);
            const float4 wB = LD4(s_w2 + (lane + 32) * 36 + c);
            const float4 v0 = LD4(hr + c);
            const float4 v1 = LD4(hr + 32 + c);
            const float4 v2 = LD4(hr + 64 + c);
            const float4 v3 = LD4(hr + 96 + c);
            FMA4(aA0, v0, wA); FMA4(aA1, v1, wA); FMA4(aA2, v2, wA); FMA4(aA3, v3, wA);
            FMA4(aB0, v0, wB); FMA4(aB1, v1, wB); FMA4(aB2, v2, wB); FMA4(aB3, v3, wB);
        }
        s_gp[(kb * 4 + 0) * 68 + lane] = aA0; s_gp[(kb * 4 + 0) * 68 + 32 + lane] = aB0;
        s_gp[(kb * 4 + 1) * 68 + lane] = aA1; s_gp[(kb * 4 + 1) * 68 + 32 + lane] = aB1;
        s_gp[(kb * 4 + 2) * 68 + lane] = aA2; s_gp[(kb * 4 + 2) * 68 + 32 + lane] = aB2;
        s_gp[(kb * 4 + 3) * 68 + lane] = aA3; s_gp[(kb * 4 + 3) * 68 + 32 + lane] = aB3;
    }
    __syncwarp();

    // ----- layer 3 + reductions -----
    float sum0 = 0.f, sum1 = 0.f, ag0 = 0.f, ag1 = 0.f;
#pragma unroll 1
    for (int kb = 0; kb < 4; kb++) {
        const float* hr = s_gp + kb * 4 * 68;
        float aA0 = s_b3[lane],      aA1 = aA0, aA2 = aA0, aA3 = aA0;
        float aB0 = s_b3[lane + 32], aB1 = aB0, aB2 = aB0, aB3 = aB0;
#pragma unroll
        for (int c = 0; c < 64; c += 4) {
            const float4 wA = LD4(s_w3 + lane * 68 + c);
            const float4 wB = LD4(s_w3 + (lane + 32) * 68 + c);
            const float4 v0 = LD4(hr + c);
            const float4 v1 = LD4(hr + 68 + c);
            const float4 v2 = LD4(hr + 136 + c);
            const float4 v3 = LD4(hr + 204 + c);
            FMA4(aA0, v0, wA); FMA4(aA1, v1, wA); FMA4(aA2, v2, wA); FMA4(aA3, v3, wA);
            FMA4(aB0, v0, wB); FMA4(aB1, v1, wB); FMA4(aB2, v2, wB); FMA4(aB3, v3, wB);
        }
        const float u0 = s_aw[kb * 4 + 0], u1 = s_aw[kb * 4 + 1];
        const float u2 = s_aw[kb * 4 + 2], u3 = s_aw[kb * 4 + 3];
        sum0 += (aA0 + aA1) + (aA2 + aA3);
        sum1 += (aB0 + aB1) + (aB2 + aB3);
        ag0 = fmaf(u0, aA0, fmaf(u1, aA1, fmaf(u2, aA2, fmaf(u3, aA3, ag0))));
        ag1 = fmaf(u0, aB0, fmaf(u1, aB1, fmaf(u2, aB2, fmaf(u3, aB3, ag1))));
    }
    const float ab = aggr_b[0];
    op[lane]       = sum0;
    op[32 + lane]  = sum1;
    op[128 + lane] = ag0 + ab;
    op[160 + lane] = ag1 + ab;
}

// ---------------------------------------------------------------------------
extern "C" void kernel_launch(void* const* d_in, const int* in_sizes, int n_in,
                              void* d_out, int out_size) {
    const float* pf     = (const float*)d_in[0];
    const float* coords = (const float*)d_in[1];
    const float* w1     = (const float*)d_in[2];
    const float* b1     = (const float*)d_in[3];
    const float* w2     = (const float*)d_in[4];
    const float* b2     = (const float*)d_in[5];
    const float* w3     = (const float*)d_in[6];
    const float* b3     = (const float*)d_in[7];
    const float* aw     = (const float*)d_in[8];
    const float* ab     = (const float*)d_in[9];
    float* out = (float*)d_out;

    knn_zero<<<1, 1024>>>();
    knn_bin<<<BB * NN / 256, 256>>>(coords);
    knn_scan<<<BB, NCELL>>>();
    knn_scatter<<<BB * NN / 256, 256>>>(coords);
    knn_main<<<BB * NN / 64, 64>>>(coords);

    const int smem = (32 * 68 + 64 * 36 + 64 * 68 + 32 + 64 + 64 + 16 +
                      8 * 1088 + 8 * 512) * (int)sizeof(float);
    cudaFuncSetAttribute(mlp_kernel, cudaFuncAttributeMaxDynamicSharedMemorySize, smem);
    mlp_kernel<<<(BB * NN) / 8, 256, smem>>>(pf, coords, w1, b1, w2, b2, w3, b3, aw, ab, out);
}

// round 3
// speedup vs baseline: 1.9757x; 1.1508x over previous
#include <cuda_runtime.h>
#include <cstdint>

#define BB   2
#define NN   8192
#define CIN  64
#define CCAT 67
#define KK   16
#define H1   32
#define H2   64
#define COUT 64

#define GRID 8            // 8x8x8 cells
#define NCELL (GRID*GRID*GRID)
#define CS   0.125f       // cell size

typedef unsigned long long u64;

__device__ int    g_knn[BB * NN * KK];
__device__ int    g_cnt[BB * NCELL];
__device__ int    g_cur[BB * NCELL];
__device__ int    g_start[BB * (NCELL + 1)];
__device__ float4 g_sorted[BB * NN];

__device__ __forceinline__ int cell_of(float x, float y, float z) {
    int ix = min(GRID - 1, max(0, (int)(x * (float)GRID)));
    int iy = min(GRID - 1, max(0, (int)(y * (float)GRID)));
    int iz = min(GRID - 1, max(0, (int)(z * (float)GRID)));
    return (iz * GRID + iy) * GRID + ix;
}

// ---------------------------------------------------------------------------
__global__ void knn_zero() {
    int t = threadIdx.x;
    if (t < BB * NCELL) g_cnt[t] = 0;
}

__global__ void knn_bin(const float* __restrict__ coords) {
    int t = blockIdx.x * blockDim.x + threadIdx.x;
    int b = t >> 13, q = t & (NN - 1);
    const float* cp = coords + ((size_t)b * NN + q) * 3;
    int c = cell_of(cp[0], cp[1], cp[2]);
    atomicAdd(&g_cnt[b * NCELL + c], 1);
}

__global__ void knn_scan() {
    __shared__ int s[NCELL];
    const int b = blockIdx.x, t = threadIdx.x;
    const int my = g_cnt[b * NCELL + t];
    s[t] = my;
    __syncthreads();
    for (int off = 1; off < NCELL; off <<= 1) {
        int v = (t >= off) ? s[t - off] : 0;
        __syncthreads();
        s[t] += v;
        __syncthreads();
    }
    g_start[b * (NCELL + 1) + t + 1] = s[t];
    if (t == 0) g_start[b * (NCELL + 1)] = 0;
    g_cur[b * NCELL + t] = s[t] - my;   // exclusive prefix = write cursor
}

__global__ void knn_scatter(const float* __restrict__ coords) {
    int t = blockIdx.x * blockDim.x + threadIdx.x;
    int b = t >> 13, q = t & (NN - 1);
    const float* cp = coords + ((size_t)b * NN + q) * 3;
    float x = cp[0], y = cp[1], z = cp[2];
    int c = cell_of(x, y, z);
    int pos = atomicAdd(&g_cur[b * NCELL + c], 1);
    g_sorted[(size_t)b * NN + pos] = make_float4(x, y, z, __int_as_float(q));
}

// ---------------------------------------------------------------------------
// Exact KNN via expanding Chebyshev rings, one thread per SORTED point so
// warp lanes share cells -> coherent ring walks and candidate loads.
// Top-16 kept as packed u64 keys (sortable(d)<<32 | idx) = exact stable
// (d, idx) ascending order, matching jax.lax.top_k tie-breaking.
// ---------------------------------------------------------------------------
__global__ __launch_bounds__(128) void knn_main() {
    const int t = blockIdx.x * 128 + threadIdx.x;
    const int b = t >> 13, slot = t & (NN - 1);
    const float4* sp = g_sorted + (size_t)b * NN;
    const float4 me = sp[slot];
    const float qx = me.x, qy = me.y, qz = me.z;
    const int   q  = __float_as_int(me.w);
    const float qsq = fmaf(qz, qz, fmaf(qy, qy, qx * qx));
    const int cx = min(GRID - 1, max(0, (int)(qx * (float)GRID)));
    const int cy = min(GRID - 1, max(0, (int)(qy * (float)GRID)));
    const int cz = min(GRID - 1, max(0, (int)(qz * (float)GRID)));

    u64 keys[KK];
#pragma unroll
    for (int j = 0; j < KK; j++) keys[j] = 0xFF80000000000000ull;  // d=+inf
    float thr = __int_as_float(0x7F800000);  // +inf

    const int* st = g_start + b * (NCELL + 1);

    for (int R = 0; R <= GRID - 1; ++R) {
        const int z0 = max(cz - R, 0), z1 = min(cz + R, GRID - 1);
        const int y0 = max(cy - R, 0), y1 = min(cy + R, GRID - 1);
        const int x0 = max(cx - R, 0), x1 = min(cx + R, GRID - 1);
        for (int z = z0; z <= z1; z++) {
            const int az = abs(z - cz);
            for (int y = y0; y <= y1; y++) {
                const int ay = max(az, abs(y - cy));
                for (int x = x0; x <= x1; x++) {
                    const int ch = max(ay, abs(x - cx));
                    if (ch != R) continue;   // ring only
                    const int c = (z * GRID + y) * GRID + x;
                    const int p1 = st[c + 1];
                    for (int p = st[c]; p < p1; ++p) {
                        const float4 cd = sp[p];
                        const float csq = fmaf(cd.z, cd.z, fmaf(cd.y, cd.y, cd.x * cd.x));
                        const float dot = fmaf(qz, cd.z, fmaf(qy, cd.y, qx * cd.x));
                        const float d = fmaf(-2.0f, dot, qsq + csq);
                        if (d < thr) {
                            unsigned s = __float_as_uint(d);
                            s ^= (unsigned)((int)s >> 31) | 0x80000000u;
                            u64 k = ((u64)s << 32) | (unsigned)__float_as_int(cd.w);
#pragma unroll
                            for (int j = 0; j < KK; j++) {   // branchless sorted insert
                                const u64 kj = keys[j];
                                const bool cl = k < kj;
                                keys[j] = cl ? k : kj;
                                k = cl ? kj : k;
                            }
                            const unsigned hs = (unsigned)(keys[KK - 1] >> 32);
                            const unsigned ob = (hs & 0x80000000u) ? (hs ^ 0x80000000u) : ~hs;
                            thr = __uint_as_float(ob);
                        }
                    }
                }
            }
        }
        const float bound = (float)R * CS;
        if (thr < bound * bound * 0.9999f) break;  // unscanned cells >= R*CS away
    }

    int* outp = g_knn + ((size_t)b * NN + q) * KK;
#pragma unroll
    for (int j = 0; j < KK; j++) outp[j] = (int)(keys[j] & 0xFFFFFFFFu);
}

// ---------------------------------------------------------------------------
// Fused gather + 3-layer MLP + (sum, max-pool, attentive-aggr).
// One warp per point, 8 points per 256-thread block, 2 blocks/SM.
// All hot math uses packed fma.rn.f32x2 (2 FMAs/issue slot).
// ---------------------------------------------------------------------------
__device__ __forceinline__ void F2(u64& d, u64 a, u64 b) {
    asm("fma.rn.f32x2 %0, %1, %2, %0;" : "+l"(d) : "l"(a), "l"(b));
}
__device__ __forceinline__ float HADD(u64 v) {
    return __uint_as_float((unsigned)v) + __uint_as_float((unsigned)(v >> 32));
}

#define LD4(p)  (*reinterpret_cast<const float4*>(p))
#define ST4(p)  (*reinterpret_cast<float4*>(p))
#define LDU2(p) (*reinterpret_cast<const ulonglong2*>(p))

__global__ __launch_bounds__(256, 2) void mlp_kernel(
    const float* __restrict__ pf, const float* __restrict__ coords,
    const float* __restrict__ w1, const float* __restrict__ b1,
    const float* __restrict__ w2, const float* __restrict__ b2,
    const float* __restrict__ w3, const float* __restrict__ b3,
    const float* __restrict__ aggr_w, const float* __restrict__ aggr_b,
    float* __restrict__ out)
{
    extern __shared__ float sm[];
    float* s_w1 = sm;                 // 32*68
    float* s_w2 = s_w1 + 32 * 68;     // 64*36
    float* s_w3 = s_w2 + 64 * 36;     // 64*68
    float* s_b1 = s_w3 + 64 * 68;     // 32
    float* s_b2 = s_b1 + 32;          // 64
    float* s_b3 = s_b2 + 64;          // 64
    float* s_aw = s_b3 + 64;          // 16
    float* s_g  = s_aw + 16;          // 8 * 1088
    float* s_h1 = s_g + 8 * 1088;     // 8 * 512

    const int tid  = threadIdx.x;
    const int lane = tid & 31;
    const int w    = tid >> 5;

    for (int i = tid; i < H1 * CCAT; i += 256) { int o = i / 67, c = i % 67; s_w1[o * 68 + c] = w1[i]; }
    for (int i = tid; i < H2 * H1;   i += 256) { int o = i >> 5, c = i & 31; s_w2[o * 36 + c] = w2[i]; }
    for (int i = tid; i < COUT * H2; i += 256) { int o = i >> 6, c = i & 63; s_w3[o * 68 + c] = w3[i]; }
    if (tid < 32) s_b1[tid] = b1[tid];
    if (tid >= 32 && tid < 96) s_b2[tid - 32] = b2[tid - 32];
    if (tid >= 96 && tid < 160) s_b3[tid - 96] = b3[tid - 96];
    if (tid >= 160 && tid < 176) s_aw[tid - 160] = aggr_w[tid - 160];
    __syncthreads();

    const int gp = blockIdx.x * 8 + w;
    const int b  = gp >> 13;
    const float* pfb = pf + (size_t)b * NN * CIN;
    const float* cob = coords + (size_t)b * NN * 3;
    const int* kn = g_knn + (size_t)gp * KK;
    float* s_gp  = s_g  + w * 1088;
    float* s_h1p = s_h1 + w * 512;

    const int nk = kn[lane & 15];

#pragma unroll
    for (int k2 = 0; k2 < KK; k2 += 2) {
        const int k = k2 + (lane >> 4);
        const int m = __shfl_sync(0xffffffffu, nk, k);
        const int cc = (lane & 15) * 4;
        const float4 v = LD4(pfb + (size_t)m * CIN + cc);
        ST4(s_gp + k * 68 + cc) = v;
    }
    if (lane < KK) {
        const float* cpp = cob + (size_t)nk * 3;
        s_gp[lane * 68 + 64] = cpp[0];
        s_gp[lane * 68 + 65] = cpp[1];
        s_gp[lane * 68 + 66] = cpp[2];
    }
    __syncwarp();
    if (lane < 3) {
        const float c0 = s_gp[64 + lane];
#pragma unroll
        for (int k = 0; k < KK; k++) s_gp[k * 68 + 64 + lane] -= c0;
    }
    __syncwarp();

    float* op = out + (size_t)gp * 192;

    // max-pool over k of raw features -> out[64..127]
    {
        const int cc = (lane & 15) * 4;
        const int k0 = (lane >> 4) * 8;
        float4 p = LD4(s_gp + k0 * 68 + cc);
#pragma unroll
        for (int k = 1; k < 8; k++) {
            const float4 v = LD4(s_gp + (k0 + k) * 68 + cc);
            p.x = fmaxf(p.x, v.x); p.y = fmaxf(p.y, v.y);
            p.z = fmaxf(p.z, v.z); p.w = fmaxf(p.w, v.w);
        }
        p.x = fmaxf(p.x, __shfl_xor_sync(0xffffffffu, p.x, 16));
        p.y = fmaxf(p.y, __shfl_xor_sync(0xffffffffu, p.y, 16));
        p.z = fmaxf(p.z, __shfl_xor_sync(0xffffffffu, p.z, 16));
        p.w = fmaxf(p.w, __shfl_xor_sync(0xffffffffu, p.w, 16));
        if (lane < 16) ST4(op + 64 + cc) = p;
    }

    // ----- layer 1: h1[k][lane] -----
#pragma unroll 1
    for (int kb = 0; kb < 4; kb++) {
        const float* gr = s_gp + kb * 4 * 68;
        u64 p0 = 0, p1 = 0, p2 = 0, p3 = 0;
#pragma unroll
        for (int c = 0; c < 64; c += 4) {
            const ulonglong2 wv = LDU2(s_w1 + lane * 68 + c);
            const ulonglong2 g0 = LDU2(gr + c);
            const ulonglong2 g1 = LDU2(gr + 68 + c);
            const ulonglong2 g2 = LDU2(gr + 136 + c);
            const ulonglong2 g3 = LDU2(gr + 204 + c);
            F2(p0, g0.x, wv.x); F2(p0, g0.y, wv.y);
            F2(p1, g1.x, wv.x); F2(p1, g1.y, wv.y);
            F2(p2, g2.x, wv.x); F2(p2, g2.y, wv.y);
            F2(p3, g3.x, wv.x); F2(p3, g3.y, wv.y);
        }
        float a0 = s_b1[lane] + HADD(p0);
        float a1 = s_b1[lane] + HADD(p1);
        float a2 = s_b1[lane] + HADD(p2);
        float a3 = s_b1[lane] + HADD(p3);
#pragma unroll
        for (int c = 64; c < 67; c++) {
            const float wv = s_w1[lane * 68 + c];
            a0 = fmaf(gr[c], wv, a0);
            a1 = fmaf(gr[68 + c], wv, a1);
            a2 = fmaf(gr[136 + c], wv, a2);
            a3 = fmaf(gr[204 + c], wv, a3);
        }
        s_h1p[(kb * 4 + 0) * 32 + lane] = a0;
        s_h1p[(kb * 4 + 1) * 32 + lane] = a1;
        s_h1p[(kb * 4 + 2) * 32 + lane] = a2;
        s_h1p[(kb * 4 + 3) * 32 + lane] = a3;
    }
    __syncwarp();

    // ----- layer 2 (h2 overlays s_gp) -----
#pragma unroll 1
    for (int kb = 0; kb < 4; kb++) {
        const float* hr = s_h1p + kb * 4 * 32;
        u64 A0 = 0, A1 = 0, A2 = 0, A3 = 0;
        u64 B0 = 0, B1 = 0, B2 = 0, B3 = 0;
#pragma unroll
        for (int c = 0; c < 32; c += 4) {
            const ulonglong2 wA = LDU2(s_w2 + lane * 36 + c);
            const ulonglong2 wB = LDU2(s_w2 + (lane + 32) * 36 + c);
            const ulonglong2 v0 = LDU2(hr + c);
            const ulonglong2 v1 = LDU2(hr + 32 + c);
            const ulonglong2 v2 = LDU2(hr + 64 + c);
            const ulonglong2 v3 = LDU2(hr + 96 + c);
            F2(A0, v0.x, wA.x); F2(A0, v0.y, wA.y);
            F2(A1, v1.x, wA.x); F2(A1, v1.y, wA.y);
            F2(A2, v2.x, wA.x); F2(A2, v2.y, wA.y);
            F2(A3, v3.x, wA.x); F2(A3, v3.y, wA.y);
            F2(B0, v0.x, wB.x); F2(B0, v0.y, wB.y);
            F2(B1, v1.x, wB.x); F2(B1, v1.y, wB.y);
            F2(B2, v2.x, wB.x); F2(B2, v2.y, wB.y);
            F2(B3, v3.x, wB.x); F2(B3, v3.y, wB.y);
        }
        const float bA = s_b2[lane], bB = s_b2[lane + 32];
        s_gp[(kb * 4 + 0) * 68 + lane] = bA + HADD(A0); s_gp[(kb * 4 + 0) * 68 + 32 + lane] = bB + HADD(B0);
        s_gp[(kb * 4 + 1) * 68 + lane] = bA + HADD(A1); s_gp[(kb * 4 + 1) * 68 + 32 + lane] = bB + HADD(B1);
        s_gp[(kb * 4 + 2) * 68 + lane] = bA + HADD(A2); s_gp[(kb * 4 + 2) * 68 + 32 + lane] = bB + HADD(B2);
        s_gp[(kb * 4 + 3) * 68 + lane] = bA + HADD(A3); s_gp[(kb * 4 + 3) * 68 + 32 + lane] = bB + HADD(B3);
    }
    __syncwarp();

    // ----- layer 3 + reductions -----
    float sum0 = 0.f, sum1 = 0.f, ag0 = 0.f, ag1 = 0.f;
#pragma unroll 1
    for (int kb = 0; kb < 4; kb++) {
        const float* hr = s_gp + kb * 4 * 68;
        u64 A0 = 0, A1 = 0, A2 = 0, A3 = 0;
        u64 B0 = 0, B1 = 0, B2 = 0, B3 = 0;
#pragma unroll
        for (int c = 0; c < 64; c += 4) {
            const ulonglong2 wA = LDU2(s_w3 + lane * 68 + c);
            const ulonglong2 wB = LDU2(s_w3 + (lane + 32) * 68 + c);
            const ulonglong2 v0 = LDU2(hr + c);
            const ulonglong2 v1 = LDU2(hr + 68 + c);
            const ulonglong2 v2 = LDU2(hr + 136 + c);
            const ulonglong2 v3 = LDU2(hr + 204 + c);
            F2(A0, v0.x, wA.x); F2(A0, v0.y, wA.y);
            F2(A1, v1.x, wA.x); F2(A1, v1.y, wA.y);
            F2(A2, v2.x, wA.x); F2(A2, v2.y, wA.y);
            F2(A3, v3.x, wA.x); F2(A3, v3.y, wA.y);
            F2(B0, v0.x, wB.x); F2(B0, v0.y, wB.y);
            F2(B1, v1.x, wB.x); F2(B1, v1.y, wB.y);
            F2(B2, v2.x, wB.x); F2(B2, v2.y, wB.y);
            F2(B3, v3.x, wB.x); F2(B3, v3.y, wB.y);
        }
        const float bA = s_b3[lane], bB = s_b3[lane + 32];
        const float aA0 = bA + HADD(A0), aA1 = bA + HADD(A1);
        const float aA2 = bA + HADD(A2), aA3 = bA + HADD(A3);
        const float aB0 = bB + HADD(B0), aB1 = bB + HADD(B1);
        const float aB2 = bB + HADD(B2), aB3 = bB + HADD(B3);
        const float u0 = s_aw[kb * 4 + 0], u1 = s_aw[kb * 4 + 1];
        const float u2 = s_aw[kb * 4 + 2], u3 = s_aw[kb * 4 + 3];
        sum0 += (aA0 + aA1) + (aA2 + aA3);
        sum1 += (aB0 + aB1) + (aB2 + aB3);
        ag0 = fmaf(u0, aA0, fmaf(u1, aA1, fmaf(u2, aA2, fmaf(u3, aA3, ag0))));
        ag1 = fmaf(u0, aB0, fmaf(u1, aB1, fmaf(u2, aB2, fmaf(u3, aB3, ag1))));
    }
    const float ab = aggr_b[0];
    op[lane]       = sum0;
    op[32 + lane]  = sum1;
    op[128 + lane] = ag0 + ab;
    op[160 + lane] = ag1 + ab;
}

// ---------------------------------------------------------------------------
extern "C" void kernel_launch(void* const* d_in, const int* in_sizes, int n_in,
                              void* d_out, int out_size) {
    const float* pf     = (const float*)d_in[0];
    const float* coords = (const float*)d_in[1];
    const float* w1     = (const float*)d_in[2];
    const float* b1     = (const float*)d_in[3];
    const float* w2     = (const float*)d_in[4];
    const float* b2     = (const float*)d_in[5];
    const float* w3     = (const float*)d_in[6];
    const float* b3     = (const float*)d_in[7];
    const float* aw     = (const float*)d_in[8];
    const float* ab     = (const float*)d_in[9];
    float* out = (float*)d_out;

    knn_zero<<<1, 1024>>>();
    knn_bin<<<BB * NN / 256, 256>>>(coords);
    knn_scan<<<BB, NCELL>>>();
    knn_scatter<<<BB * NN / 256, 256>>>(coords);
    knn_main<<<BB * NN / 128, 128>>>();

    const int smem = (32 * 68 + 64 * 36 + 64 * 68 + 32 + 64 + 64 + 16 +
                      8 * 1088 + 8 * 512) * (int)sizeof(float);
    cudaFuncSetAttribute(mlp_kernel, cudaFuncAttributeMaxDynamicSharedMemorySize, smem);
    mlp_kernel<<<(BB * NN) / 8, 256, smem>>>(pf, coords, w1, b1, w2, b2, w3, b3, aw, ab, out);
}

// round 4
// speedup vs baseline: 2.5510x; 1.2911x over previous
#include <cuda_runtime.h>
#include <cstdint>

#define BB   2
#define NN   8192
#define CIN  64
#define CCAT 67
#define KK   16
#define H1   32
#define H2   64
#define COUT 64

#define GRID 8            // 8x8x8 cells
#define NCELL (GRID*GRID*GRID)
#define CS   0.125f       // cell size

typedef unsigned long long u64;

__device__ int    g_knn[BB * NN * KK];
__device__ int    g_cnt[BB * NCELL];          // zero-initialized; scan resets it
__device__ int    g_start[BB * (NCELL + 1)];
__device__ float4 g_sorted[BB * NN];

__device__ __forceinline__ int cell_of(float x, float y, float z) {
    int ix = min(GRID - 1, max(0, (int)(x * (float)GRID)));
    int iy = min(GRID - 1, max(0, (int)(y * (float)GRID)));
    int iz = min(GRID - 1, max(0, (int)(z * (float)GRID)));
    return (iz * GRID + iy) * GRID + ix;
}

// ---------------------------------------------------------------------------
__global__ void knn_bin(const float* __restrict__ coords) {
    int t = blockIdx.x * blockDim.x + threadIdx.x;
    int b = t >> 13, q = t & (NN - 1);
    const float* cp = coords + ((size_t)b * NN + q) * 3;
    int c = cell_of(cp[0], cp[1], cp[2]);
    atomicAdd(&g_cnt[b * NCELL + c], 1);
}

// scan + scatter fused; also resets g_cnt for the next graph replay.
__global__ __launch_bounds__(NCELL) void knn_scan_scatter(const float* __restrict__ coords) {
    __shared__ int s[NCELL];
    __shared__ int cur[NCELL];
    const int b = blockIdx.x, t = threadIdx.x;
    const int my = g_cnt[b * NCELL + t];
    s[t] = my;
    __syncthreads();
    for (int off = 1; off < NCELL; off <<= 1) {
        int v = (t >= off) ? s[t - off] : 0;
        __syncthreads();
        s[t] += v;
        __syncthreads();
    }
    g_start[b * (NCELL + 1) + t + 1] = s[t];
    if (t == 0) g_start[b * (NCELL + 1)] = 0;
    cur[t] = s[t] - my;            // exclusive prefix = write cursor
    g_cnt[b * NCELL + t] = 0;      // reset for next call
    __syncthreads();
    for (int q = t; q < NN; q += NCELL) {
        const float* cp = coords + ((size_t)b * NN + q) * 3;
        float x = cp[0], y = cp[1], z = cp[2];
        int c = cell_of(x, y, z);
        int pos = atomicAdd(&cur[c], 1);
        g_sorted[(size_t)b * NN + pos] = make_float4(x, y, z, __int_as_float(q));
    }
}

// ---------------------------------------------------------------------------
// Exact KNN via expanding Chebyshev rings, one thread per SORTED point so
// warp lanes share cells. Full ring rows scanned as ONE contiguous stream.
// Top-16 kept as packed u64 keys (sortable(d)<<32 | idx) = exact stable
// (d, idx) ascending order, matching jax.lax.top_k tie-breaking.
// ---------------------------------------------------------------------------
__global__ __launch_bounds__(128) void knn_main() {
    const int t = blockIdx.x * 128 + threadIdx.x;
    const int b = t >> 13, slot = t & (NN - 1);
    const float4* sp = g_sorted + (size_t)b * NN;
    const float4 me = sp[slot];
    const float qx = me.x, qy = me.y, qz = me.z;
    const int   q  = __float_as_int(me.w);
    const float qsq = fmaf(qz, qz, fmaf(qy, qy, qx * qx));
    const int cx = min(GRID - 1, max(0, (int)(qx * (float)GRID)));
    const int cy = min(GRID - 1, max(0, (int)(qy * (float)GRID)));
    const int cz = min(GRID - 1, max(0, (int)(qz * (float)GRID)));

    u64 keys[KK];
#pragma unroll
    for (int j = 0; j < KK; j++) keys[j] = 0xFF80000000000000ull;  // d=+inf
    float thr = __int_as_float(0x7F800000);  // +inf

    const int* st = g_start + b * (NCELL + 1);

#define SCAN_RANGE(PA, PB)                                                     \
    for (int p = (PA); p < (PB); ++p) {                                        \
        const float4 cd = sp[p];                                               \
        const float csq = fmaf(cd.z, cd.z, fmaf(cd.y, cd.y, cd.x * cd.x));     \
        const float dot = fmaf(qz, cd.z, fmaf(qy, cd.y, qx * cd.x));           \
        const float d = fmaf(-2.0f, dot, qsq + csq);                           \
        if (d < thr) {                                                         \
            unsigned s_ = __float_as_uint(d);                                  \
            s_ ^= (unsigned)((int)s_ >> 31) | 0x80000000u;                     \
            u64 k_ = ((u64)s_ << 32) | (unsigned)__float_as_int(cd.w);         \
            _Pragma("unroll")                                                  \
            for (int j = 0; j < KK; j++) {                                     \
                const u64 kj = keys[j];                                        \
                const bool cl = k_ < kj;                                       \
                keys[j] = cl ? k_ : kj;                                        \
                k_ = cl ? kj : k_;                                             \
            }                                                                  \
            const unsigned hs = (unsigned)(keys[KK - 1] >> 32);                \
            const unsigned ob = (hs & 0x80000000u) ? (hs ^ 0x80000000u) : ~hs; \
            thr = __uint_as_float(ob);                                         \
        }                                                                      \
    }

    for (int R = 0; R <= GRID - 1; ++R) {
        const int z0 = max(cz - R, 0), z1 = min(cz + R, GRID - 1);
        const int y0 = max(cy - R, 0), y1 = min(cy + R, GRID - 1);
        const int x0 = max(cx - R, 0), x1 = min(cx + R, GRID - 1);
        for (int z = z0; z <= z1; z++) {
            const int az = abs(z - cz);
            for (int y = y0; y <= y1; y++) {
                const int m2 = max(az, abs(y - cy));
                const int rowbase = (z * GRID + y) * GRID;
                if (m2 == R) {
                    // whole row is on the ring: contiguous candidate stream
                    const int pa = st[rowbase + x0];
                    const int pb = st[rowbase + x1 + 1];
                    SCAN_RANGE(pa, pb)
                } else {
                    // only the two x-extremes are on the ring
                    const int xl = cx - R, xr = cx + R;
                    if (xl >= 0) {
                        const int pa = st[rowbase + xl];
                        const int pb = st[rowbase + xl + 1];
                        SCAN_RANGE(pa, pb)
                    }
                    if (xr <= GRID - 1) {
                        const int pa = st[rowbase + xr];
                        const int pb = st[rowbase + xr + 1];
                        SCAN_RANGE(pa, pb)
                    }
                }
            }
        }
        const float bound = (float)R * CS;
        if (thr < bound * bound * 0.9999f) break;  // unscanned cells >= R*CS away
    }
#undef SCAN_RANGE

    int* outp = g_knn + ((size_t)b * NN + q) * KK;
#pragma unroll
    for (int j = 0; j < KK; j++) outp[j] = (int)(keys[j] & 0xFFFFFFFFu);
}

// ---------------------------------------------------------------------------
// Fused gather + 3-layer MLP + (sum, max-pool, attentive-aggr).
// One warp per point. k-block = 16: each weight LDS.128 feeds all 16 k-rows,
// minimizing shared-crossbar traffic (the measured binder).
// ---------------------------------------------------------------------------
__device__ __forceinline__ void F2(u64& d, u64 a, u64 b) {
    asm("fma.rn.f32x2 %0, %1, %2, %0;" : "+l"(d) : "l"(a), "l"(b));
}
__device__ __forceinline__ float HADD(u64 v) {
    return __uint_as_float((unsigned)v) + __uint_as_float((unsigned)(v >> 32));
}

#define LD4(p)  (*reinterpret_cast<const float4*>(p))
#define ST4(p)  (*reinterpret_cast<float4*>(p))
#define LDU2(p) (*reinterpret_cast<const ulonglong2*>(p))

__global__ __launch_bounds__(256, 2) void mlp_kernel(
    const float* __restrict__ pf, const float* __restrict__ coords,
    const float* __restrict__ w1, const float* __restrict__ b1,
    const float* __restrict__ w2, const float* __restrict__ b2,
    const float* __restrict__ w3, const float* __restrict__ b3,
    const float* __restrict__ aggr_w, const float* __restrict__ aggr_b,
    float* __restrict__ out)
{
    extern __shared__ float sm[];
    float* s_w1 = sm;                 // 32*68
    float* s_w2 = s_w1 + 32 * 68;     // 64*36
    float* s_w3 = s_w2 + 64 * 36;     // 64*68
    float* s_b1 = s_w3 + 64 * 68;     // 32
    float* s_b2 = s_b1 + 32;          // 64
    float* s_b3 = s_b2 + 64;          // 64
    float* s_aw = s_b3 + 64;          // 16
    float* s_g  = s_aw + 16;          // 8 * 1088
    float* s_h1 = s_g + 8 * 1088;     // 8 * 512

    const int tid  = threadIdx.x;
    const int lane = tid & 31;
    const int w    = tid >> 5;

    for (int i = tid; i < H1 * CCAT; i += 256) { int o = i / 67, c = i % 67; s_w1[o * 68 + c] = w1[i]; }
    for (int i = tid; i < H2 * H1;   i += 256) { int o = i >> 5, c = i & 31; s_w2[o * 36 + c] = w2[i]; }
    for (int i = tid; i < COUT * H2; i += 256) { int o = i >> 6, c = i & 63; s_w3[o * 68 + c] = w3[i]; }
    if (tid < 32) s_b1[tid] = b1[tid];
    if (tid >= 32 && tid < 96) s_b2[tid - 32] = b2[tid - 32];
    if (tid >= 96 && tid < 160) s_b3[tid - 96] = b3[tid - 96];
    if (tid >= 160 && tid < 176) s_aw[tid - 160] = aggr_w[tid - 160];
    __syncthreads();

    const int gp = blockIdx.x * 8 + w;
    const int b  = gp >> 13;
    const float* pfb = pf + (size_t)b * NN * CIN;
    const float* cob = coords + (size_t)b * NN * 3;
    const int* kn = g_knn + (size_t)gp * KK;
    float* s_gp  = s_g  + w * 1088;
    float* s_h1p = s_h1 + w * 512;

    const int nk = kn[lane & 15];

#pragma unroll
    for (int k2 = 0; k2 < KK; k2 += 2) {
        const int k = k2 + (lane >> 4);
        const int m = __shfl_sync(0xffffffffu, nk, k);
        const int cc = (lane & 15) * 4;
        const float4 v = LD4(pfb + (size_t)m * CIN + cc);
        ST4(s_gp + k * 68 + cc) = v;
    }
    if (lane < KK) {
        const float* cpp = cob + (size_t)nk * 3;
        s_gp[lane * 68 + 64] = cpp[0];
        s_gp[lane * 68 + 65] = cpp[1];
        s_gp[lane * 68 + 66] = cpp[2];
    }
    __syncwarp();
    if (lane < 3) {
        const float c0 = s_gp[64 + lane];
#pragma unroll
        for (int k = 0; k < KK; k++) s_gp[k * 68 + 64 + lane] -= c0;
    }
    __syncwarp();

    float* op = out + (size_t)gp * 192;

    // max-pool over k of raw features -> out[64..127]
    {
        const int cc = (lane & 15) * 4;
        const int k0 = (lane >> 4) * 8;
        float4 p = LD4(s_gp + k0 * 68 + cc);
#pragma unroll
        for (int k = 1; k < 8; k++) {
            const float4 v = LD4(s_gp + (k0 + k) * 68 + cc);
            p.x = fmaxf(p.x, v.x); p.y = fmaxf(p.y, v.y);
            p.z = fmaxf(p.z, v.z); p.w = fmaxf(p.w, v.w);
        }
        p.x = fmaxf(p.x, __shfl_xor_sync(0xffffffffu, p.x, 16));
        p.y = fmaxf(p.y, __shfl_xor_sync(0xffffffffu, p.y, 16));
        p.z = fmaxf(p.z, __shfl_xor_sync(0xffffffffu, p.z, 16));
        p.w = fmaxf(p.w, __shfl_xor_sync(0xffffffffu, p.w, 16));
        if (lane < 16) ST4(op + 64 + cc) = p;
    }

    // ----- layer 1: h1[k][lane], all 16 k per weight load -----
    {
        u64 p[KK];
#pragma unroll
        for (int k = 0; k < KK; k++) p[k] = 0;
#pragma unroll
        for (int c = 0; c < 64; c += 4) {
            const ulonglong2 wv = LDU2(s_w1 + lane * 68 + c);
#pragma unroll
            for (int k = 0; k < KK; k++) {
                const ulonglong2 g = LDU2(s_gp + k * 68 + c);
                F2(p[k], g.x, wv.x); F2(p[k], g.y, wv.y);
            }
        }
        float h[KK];
        const float bb = s_b1[lane];
#pragma unroll
        for (int k = 0; k < KK; k++) h[k] = bb + HADD(p[k]);
#pragma unroll
        for (int c = 64; c < 67; c++) {
            const float wt = s_w1[lane * 68 + c];
#pragma unroll
            for (int k = 0; k < KK; k++) h[k] = fmaf(s_gp[k * 68 + c], wt, h[k]);
        }
#pragma unroll
        for (int k = 0; k < KK; k++) s_h1p[k * 32 + lane] = h[k];
    }
    __syncwarp();

    // ----- layer 2 (h2 overlays s_gp) -----
    {
        u64 A[KK], B[KK];
#pragma unroll
        for (int k = 0; k < KK; k++) { A[k] = 0; B[k] = 0; }
#pragma unroll
        for (int c = 0; c < 32; c += 4) {
            const ulonglong2 wA = LDU2(s_w2 + lane * 36 + c);
            const ulonglong2 wB = LDU2(s_w2 + (lane + 32) * 36 + c);
#pragma unroll
            for (int k = 0; k < KK; k++) {
                const ulonglong2 v = LDU2(s_h1p + k * 32 + c);
                F2(A[k], v.x, wA.x); F2(A[k], v.y, wA.y);
                F2(B[k], v.x, wB.x); F2(B[k], v.y, wB.y);
            }
        }
        const float bA = s_b2[lane], bB = s_b2[lane + 32];
#pragma unroll
        for (int k = 0; k < KK; k++) {
            s_gp[k * 68 + lane]      = bA + HADD(A[k]);
            s_gp[k * 68 + 32 + lane] = bB + HADD(B[k]);
        }
    }
    __syncwarp();

    // ----- layer 3 + reductions -----
    {
        u64 A[KK], B[KK];
#pragma unroll
        for (int k = 0; k < KK; k++) { A[k] = 0; B[k] = 0; }
#pragma unroll
        for (int c = 0; c < 64; c += 4) {
            const ulonglong2 wA = LDU2(s_w3 + lane * 68 + c);
            const ulonglong2 wB = LDU2(s_w3 + (lane + 32) * 68 + c);
#pragma unroll
            for (int k = 0; k < KK; k++) {
                const ulonglong2 v = LDU2(s_gp + k * 68 + c);
                F2(A[k], v.x, wA.x); F2(A[k], v.y, wA.y);
                F2(B[k], v.x, wB.x); F2(B[k], v.y, wB.y);
            }
        }
        const float bA = s_b3[lane], bB = s_b3[lane + 32];
        float sum0 = 0.f, sum1 = 0.f, ag0 = 0.f, ag1 = 0.f;
#pragma unroll
        for (int k = 0; k < KK; k++) {
            const float aA = bA + HADD(A[k]);
            const float aB = bB + HADD(B[k]);
            const float u = s_aw[k];
            sum0 += aA; sum1 += aB;
            ag0 = fmaf(u, aA, ag0);
            ag1 = fmaf(u, aB, ag1);
        }
        const float ab = aggr_b[0];
        op[lane]       = sum0;
        op[32 + lane]  = sum1;
        op[128 + lane] = ag0 + ab;
        op[160 + lane] = ag1 + ab;
    }
}

// ---------------------------------------------------------------------------
extern "C" void kernel_launch(void* const* d_in, const int* in_sizes, int n_in,
                              void* d_out, int out_size) {
    const float* pf     = (const float*)d_in[0];
    const float* coords = (const float*)d_in[1];
    const float* w1     = (const float*)d_in[2];
    const float* b1     = (const float*)d_in[3];
    const float* w2     = (const float*)d_in[4];
    const float* b2     = (const float*)d_in[5];
    const float* w3     = (const float*)d_in[6];
    const float* b3     = (const float*)d_in[7];
    const float* aw     = (const float*)d_in[8];
    const float* ab     = (const float*)d_in[9];
    float* out = (float*)d_out;

    knn_bin<<<BB * NN / 256, 256>>>(coords);
    knn_scan_scatter<<<BB, NCELL>>>(coords);
    knn_main<<<BB * NN / 128, 128>>>();

    const int smem = (32 * 68 + 64 * 36 + 64 * 68 + 32 + 64 + 64 + 16 +
                      8 * 1088 + 8 * 512) * (int)sizeof(float);
    cudaFuncSetAttribute(mlp_kernel, cudaFuncAttributeMaxDynamicSharedMemorySize, smem);
    mlp_kernel<<<(BB * NN) / 8, 256, smem>>>(pf, coords, w1, b1, w2, b2, w3, b3, aw, ab, out);
}

// round 6
// speedup vs baseline: 2.8533x; 1.1185x over previous
#include <cuda_runtime.h>
#include <cstdint>

#define BB   2
#define NN   8192
#define CIN  64
#define CCAT 67
#define KK   16
#define H1   32
#define H2   64
#define COUT 64

#define GRID 8            // 8x8x8 cells
#define NCELL (GRID*GRID*GRID)
#define CS   0.125f       // cell size

typedef unsigned long long u64;

__device__ int    g_knn[BB * NN * KK];
__device__ int    g_cnt[BB * NCELL];          // zero-initialized; scan resets it
__device__ int    g_start[BB * (NCELL + 1)];
__device__ float4 g_sorted[BB * NN];
__device__ float  g_W[COUT * 68];             // collapsed MLP matrix, col 67 = 0
__device__ float  g_C1[COUT];                 // 16 * B
__device__ float  g_C2[COUT];                 // sum(aggr_w) * B + aggr_b

__device__ __forceinline__ int cell_of(float x, float y, float z) {
    int ix = min(GRID - 1, max(0, (int)(x * (float)GRID)));
    int iy = min(GRID - 1, max(0, (int)(y * (float)GRID)));
    int iz = min(GRID - 1, max(0, (int)(z * (float)GRID)));
    return (iz * GRID + iy) * GRID + ix;
}

// ---------------------------------------------------------------------------
// Collapse the affine MLP:  W = w3*w2*w1,  B = w3*(w2*b1 + b2) + b3
// ---------------------------------------------------------------------------
__global__ __launch_bounds__(256) void precomp(
    const float* __restrict__ w1, const float* __restrict__ b1,
    const float* __restrict__ w2, const float* __restrict__ b2,
    const float* __restrict__ w3, const float* __restrict__ b3,
    const float* __restrict__ aggr_w, const float* __restrict__ aggr_b)
{
    __shared__ float s0[4192];       // w1(2144)+w2(2048); later reused for w3(4096)
    __shared__ float s21[64 * 67];   // w2*w1
    __shared__ float st[64];         // w2*b1 + b2
    __shared__ float s_sumU;
    float* sw1 = s0;
    float* sw2 = s0 + 2144;
    const int t = threadIdx.x;
    for (int i = t; i < 2144; i += 256) sw1[i] = w1[i];
    for (int i = t; i < 2048; i += 256) sw2[i] = w2[i];
    if (t == 0) {
        float s = 0.f;
        for (int k = 0; k < KK; k++) s += aggr_w[k];
        s_sumU = s;
    }
    __syncthreads();
    if (t < 64) {
        float acc = b2[t];
        for (int j = 0; j < 32; j++) acc = fmaf(sw2[t * 32 + j], b1[j], acc);
        st[t] = acc;
    }
    for (int i = t; i < 64 * 67; i += 256) {
        int o = i / 67, c = i % 67;
        float acc = 0.f;
        for (int j = 0; j < 32; j++) acc = fmaf(sw2[o * 32 + j], sw1[j * 67 + c], acc);
        s21[i] = acc;
    }
    __syncthreads();
    float* sw3 = s0;                 // overlay (w1/w2 dead)
    for (int i = t; i < 4096; i += 256) sw3[i] = w3[i];
    __syncthreads();
    for (int i = t; i < 64 * 68; i += 256) {
        int o = i / 68, c = i % 68;
        float acc = 0.f;
        if (c < 67)
            for (int j = 0; j < 64; j++) acc = fmaf(sw3[o * 64 + j], s21[j * 67 + c], acc);
        g_W[i] = acc;                // col 67 stays 0 (pad)
    }
    if (t < 64) {
        float B = b3[t];
        for (int j = 0; j < 64; j++) B = fmaf(sw3[t * 64 + j], st[j], B);
        g_C1[t] = 16.0f * B;
        g_C2[t] = fmaf(s_sumU, B, aggr_b[0]);
    }
}

// ---------------------------------------------------------------------------
__global__ void knn_bin(const float* __restrict__ coords) {
    int t = blockIdx.x * blockDim.x + threadIdx.x;
    int b = t >> 13, q = t & (NN - 1);
    const float* cp = coords + ((size_t)b * NN + q) * 3;
    int c = cell_of(cp[0], cp[1], cp[2]);
    atomicAdd(&g_cnt[b * NCELL + c], 1);
}

__global__ __launch_bounds__(NCELL) void knn_scan_scatter(const float* __restrict__ coords) {
    __shared__ int s[NCELL];
    __shared__ int cur[NCELL];
    const int b = blockIdx.x, t = threadIdx.x;
    const int my = g_cnt[b * NCELL + t];
    s[t] = my;
    __syncthreads();
    for (int off = 1; off < NCELL; off <<= 1) {
        int v = (t >= off) ? s[t - off] : 0;
        __syncthreads();
        s[t] += v;
        __syncthreads();
    }
    g_start[b * (NCELL + 1) + t + 1] = s[t];
    if (t == 0) g_start[b * (NCELL + 1)] = 0;
    cur[t] = s[t] - my;
    g_cnt[b * NCELL + t] = 0;      // reset for next replay
    __syncthreads();
    for (int q = t; q < NN; q += NCELL) {
        const float* cp = coords + ((size_t)b * NN + q) * 3;
        float x = cp[0], y = cp[1], z = cp[2];
        int c = cell_of(x, y, z);
        int pos = atomicAdd(&cur[c], 1);
        g_sorted[(size_t)b * NN + pos] = make_float4(x, y, z, __int_as_float(q));
    }
}

// ---------------------------------------------------------------------------
// Exact KNN: 2 threads per query (candidate parity slices), expanding
// Chebyshev rings over sorted points, exact bitonic merge of the two
// sorted top-16 u64 key lists ((sortable(d)<<32)|idx).
// ---------------------------------------------------------------------------
__device__ __forceinline__ u64 u64min(u64 a, u64 b) { return a < b ? a : b; }
__device__ __forceinline__ u64 u64max(u64 a, u64 b) { return a < b ? b : a; }

__global__ __launch_bounds__(128) void knn_main() {
    const int tt = blockIdx.x * 128 + threadIdx.x;
    const int pt = tt >> 1;           // query point
    const int parity = tt & 1;        // candidate slice
    const int b = pt >> 13, slot = pt & (NN - 1);
    const float4* sp = g_sorted + (size_t)b * NN;
    const float4 me = sp[slot];
    const float qx = me.x, qy = me.y, qz = me.z;
    const int   q  = __float_as_int(me.w);
    const float qsq = fmaf(qz, qz, fmaf(qy, qy, qx * qx));
    const int cx = min(GRID - 1, max(0, (int)(qx * (float)GRID)));
    const int cy = min(GRID - 1, max(0, (int)(qy * (float)GRID)));
    const int cz = min(GRID - 1, max(0, (int)(qz * (float)GRID)));

    u64 keys[KK];
#pragma unroll
    for (int j = 0; j < KK; j++) keys[j] = 0xFF80000000000000ull;  // +inf
    float thr = __int_as_float(0x7F800000);

    const int* st = g_start + b * (NCELL + 1);

#define SCAN_RANGE(PA, PB)                                                     \
    for (int p = (PA) + (((PA) & 1) ^ parity); p < (PB); p += 2) {             \
        const float4 cd = sp[p];                                               \
        const float csq = fmaf(cd.z, cd.z, fmaf(cd.y, cd.y, cd.x * cd.x));     \
        const float dot = fmaf(qz, cd.z, fmaf(qy, cd.y, qx * cd.x));           \
        const float d = fmaf(-2.0f, dot, qsq + csq);                           \
        if (d < thr) {                                                         \
            unsigned s_ = __float_as_uint(d);                                  \
            s_ ^= (unsigned)((int)s_ >> 31) | 0x80000000u;                     \
            u64 k_ = ((u64)s_ << 32) | (unsigned)__float_as_int(cd.w);         \
            _Pragma("unroll")                                                  \
            for (int j = 0; j < KK; j++) {                                     \
                const u64 kj = keys[j];                                        \
                const bool cl = k_ < kj;                                       \
                keys[j] = cl ? k_ : kj;                                        \
                k_ = cl ? kj : k_;                                             \
            }                                                                  \
            const unsigned hs = (unsigned)(keys[KK - 1] >> 32);                \
            const unsigned ob = (hs & 0x80000000u) ? (hs ^ 0x80000000u) : ~hs; \
            thr = __uint_as_float(ob);                                         \
        }                                                                      \
    }

    for (int R = 0; R <= GRID - 1; ++R) {
        const int z0 = max(cz - R, 0), z1 = min(cz + R, GRID - 1);
        const int y0 = max(cy - R, 0), y1 = min(cy + R, GRID - 1);
        const int x0 = max(cx - R, 0), x1 = min(cx + R, GRID - 1);
        for (int z = z0; z <= z1; z++) {
            const int az = abs(z - cz);
            for (int y = y0; y <= y1; y++) {
                const int m2 = max(az, abs(y - cy));
                const int rowbase = (z * GRID + y) * GRID;
                if (m2 == R) {
                    const int pa = st[rowbase + x0];
                    const int pb = st[rowbase + x1 + 1];
                    SCAN_RANGE(pa, pb)
                } else {
                    const int xl = cx - R, xr = cx + R;
                    if (xl >= 0) {
                        const int pa = st[rowbase + xl];
                        const int pb = st[rowbase + xl + 1];
                        SCAN_RANGE(pa, pb)
                    }
                    if (xr <= GRID - 1) {
                        const int pa = st[rowbase + xr];
                        const int pb = st[rowbase + xr + 1];
                        SCAN_RANGE(pa, pb)
                    }
                }
            }
        }
        const float bound = (float)R * CS;
        if (thr < bound * bound * 0.9999f) break;   // safe per-slice (thr >= merged thr)
    }
#undef SCAN_RANGE

    // exact merge of the two sorted slice lists (lanes lane^1 are partners)
    u64 m[KK];
#pragma unroll
    for (int i = 0; i < KK; i++) {
        const u64 pk = __shfl_xor_sync(0xffffffffu, keys[KK - 1 - i], 1);
        m[i] = u64min(keys[i], pk);   // 16 smallest, bitonic order
    }
#pragma unroll
    for (int s = 8; s >= 1; s >>= 1) {
#pragma unroll
        for (int i = 0; i < KK; i++) {
            if ((i & s) == 0) {
                const u64 lo = u64min(m[i], m[i + s]);
                const u64 hi = u64max(m[i], m[i + s]);
                m[i] = lo; m[i + s] = hi;
            }
        }
    }
    if (parity == 0) {
        int* outp = g_knn + ((size_t)b * NN + q) * KK;
#pragma unroll
        for (int j = 0; j < KK; j++) outp[j] = (int)(m[j] & 0xFFFFFFFFu);
    }
}

// ---------------------------------------------------------------------------
// Fused gather + collapsed-affine evaluation:
//   out_sum = W*s1 + C1,  pool = max_k g_k[:64],  aggr = W*s2 + C2
//   s1 = sum_k g_k,  s2 = sum_k aggr_w[k] * g_k   (rel coords in last 3)
// One warp per point; sums accumulate in registers during the gather.
// ---------------------------------------------------------------------------
__device__ __forceinline__ void F2(u64& d, u64 a, u64 b) {
    asm("fma.rn.f32x2 %0, %1, %2, %0;" : "+l"(d) : "l"(a), "l"(b));
}
__device__ __forceinline__ float HADD(u64 v) {
    return __uint_as_float((unsigned)v) + __uint_as_float((unsigned)(v >> 32));
}
#define LD4(p)  (*reinterpret_cast<const float4*>(p))
#define LDU2(p) (*reinterpret_cast<const ulonglong2*>(p))

__global__ __launch_bounds__(256) void mlp2_kernel(
    const float* __restrict__ pf, const float* __restrict__ coords,
    const float* __restrict__ aggr_w, float* __restrict__ out)
{
    __shared__ __align__(16) float s_W[COUT * 68];
    __shared__ float s_C1[COUT], s_C2[COUT], s_u[KK];
    __shared__ __align__(16) float s_s[8][2][68];

    const int tid  = threadIdx.x;
    const int lane = tid & 31;
    const int w    = tid >> 5;

    for (int i = tid; i < COUT * 68; i += 256) s_W[i] = g_W[i];
    if (tid < 64) s_C1[tid] = g_C1[tid];
    else if (tid < 128) s_C2[tid - 64] = g_C2[tid - 64];
    else if (tid < 144) s_u[tid - 128] = aggr_w[tid - 128];
    __syncthreads();

    const int gp = blockIdx.x * 8 + w;
    const int b  = gp >> 13;
    const float* pfb = pf + (size_t)b * NN * CIN;
    const float* cob = coords + (size_t)b * NN * 3;

    const int nk = g_knn[(size_t)gp * KK + (lane & 15)];
    const int cc = (lane & 15) * 4;

    float4 pool = make_float4(-3.4e38f, -3.4e38f, -3.4e38f, -3.4e38f);
    float4 a1 = make_float4(0.f, 0.f, 0.f, 0.f);
    float4 a2 = a1;
#pragma unroll
    for (int k2 = 0; k2 < KK; k2 += 2) {
        const int k = k2 + (lane >> 4);
        const int m = __shfl_sync(0xffffffffu, nk, k);
        const float u = s_u[k];
        const float4 v = LD4(pfb + (size_t)m * CIN + cc);
        pool.x = fmaxf(pool.x, v.x); pool.y = fmaxf(pool.y, v.y);
        pool.z = fmaxf(pool.z, v.z); pool.w = fmaxf(pool.w, v.w);
        a1.x += v.x; a1.y += v.y; a1.z += v.z; a1.w += v.w;
        a2.x = fmaf(u, v.x, a2.x); a2.y = fmaf(u, v.y, a2.y);
        a2.z = fmaf(u, v.z, a2.z); a2.w = fmaf(u, v.w, a2.w);
    }
    // combine the two k-halves (lane <-> lane+16)
    pool.x = fmaxf(pool.x, __shfl_xor_sync(0xffffffffu, pool.x, 16));
    pool.y = fmaxf(pool.y, __shfl_xor_sync(0xffffffffu, pool.y, 16));
    pool.z = fmaxf(pool.z, __shfl_xor_sync(0xffffffffu, pool.z, 16));
    pool.w = fmaxf(pool.w, __shfl_xor_sync(0xffffffffu, pool.w, 16));
    a1.x += __shfl_xor_sync(0xffffffffu, a1.x, 16);
    a1.y += __shfl_xor_sync(0xffffffffu, a1.y, 16);
    a1.z += __shfl_xor_sync(0xffffffffu, a1.z, 16);
    a1.w += __shfl_xor_sync(0xffffffffu, a1.w, 16);
    a2.x += __shfl_xor_sync(0xffffffffu, a2.x, 16);
    a2.y += __shfl_xor_sync(0xffffffffu, a2.y, 16);
    a2.z += __shfl_xor_sync(0xffffffffu, a2.z, 16);
    a2.w += __shfl_xor_sync(0xffffffffu, a2.w, 16);

    // relative-coord channel sums (channels 64..66)
    const int m0 = __shfl_sync(0xffffffffu, nk, 0);
    const float c0x = cob[(size_t)m0 * 3 + 0];
    const float c0y = cob[(size_t)m0 * 3 + 1];
    const float c0z = cob[(size_t)m0 * 3 + 2];
    float dx = 0.f, dy = 0.f, dz = 0.f, ex = 0.f, ey = 0.f, ez = 0.f;
    if (lane < KK) {
        const float* cp = cob + (size_t)nk * 3;
        dx = cp[0] - c0x; dy = cp[1] - c0y; dz = cp[2] - c0z;
        const float u = s_u[lane];
        ex = u * dx; ey = u * dy; ez = u * dz;
    }
#pragma unroll
    for (int s = 8; s >= 1; s >>= 1) {
        dx += __shfl_xor_sync(0xffffffffu, dx, s);
        dy += __shfl_xor_sync(0xffffffffu, dy, s);
        dz += __shfl_xor_sync(0xffffffffu, dz, s);
        ex += __shfl_xor_sync(0xffffffffu, ex, s);
        ey += __shfl_xor_sync(0xffffffffu, ey, s);
        ez += __shfl_xor_sync(0xffffffffu, ez, s);
    }

    if (lane < 16) {
        *reinterpret_cast<float4*>(&s_s[w][0][cc]) = a1;
        *reinterpret_cast<float4*>(&s_s[w][1][cc]) = a2;
    }
    if (lane == 0) {
        s_s[w][0][64] = dx; s_s[w][0][65] = dy; s_s[w][0][66] = dz; s_s[w][0][67] = 0.f;
        s_s[w][1][64] = ex; s_s[w][1][65] = ey; s_s[w][1][66] = ez; s_s[w][1][67] = 0.f;
    }
    __syncwarp();

    // two 64x67 matvecs: lane handles outputs (lane, lane+32) for s1 and s2
    u64 A1 = 0, B1 = 0, A2 = 0, B2 = 0;
#pragma unroll
    for (int c = 0; c < 68; c += 4) {
        const ulonglong2 wA = LDU2(s_W + lane * 68 + c);
        const ulonglong2 wB = LDU2(s_W + (lane + 32) * 68 + c);
        const ulonglong2 x1 = LDU2(&s_s[w][0][c]);
        const ulonglong2 x2 = LDU2(&s_s[w][1][c]);
        F2(A1, x1.x, wA.x); F2(A1, x1.y, wA.y);
        F2(B1, x1.x, wB.x); F2(B1, x1.y, wB.y);
        F2(A2, x2.x, wA.x); F2(A2, x2.y, wA.y);
        F2(B2, x2.x, wB.x); F2(B2, x2.y, wB.y);
    }

    float* op = out + (size_t)gp * 192;
    op[lane]        = HADD(A1) + s_C1[lane];
    op[32 + lane]   = HADD(B1) + s_C1[lane + 32];
    op[128 + lane]  = HADD(A2) + s_C2[lane];
    op[160 + lane]  = HADD(B2) + s_C2[lane + 32];
    if (lane < 16) *reinterpret_cast<float4*>(op + 64 + cc) = pool;
}

// ---------------------------------------------------------------------------
extern "C" void kernel_launch(void* const* d_in, const int* in_sizes, int n_in,
                              void* d_out, int out_size) {
    const float* pf     = (const float*)d_in[0];
    const float* coords = (const float*)d_in[1];
    const float* w1     = (const float*)d_in[2];
    const float* b1     = (const float*)d_in[3];
    const float* w2     = (const float*)d_in[4];
    const float* b2     = (const float*)d_in[5];
    const float* w3     = (const float*)d_in[6];
    const float* b3     = (const float*)d_in[7];
    const float* aw     = (const float*)d_in[8];
    const float* ab     = (const float*)d_in[9];
    float* out = (float*)d_out;

    precomp<<<1, 256>>>(w1, b1, w2, b2, w3, b3, aw, ab);
    knn_bin<<<BB * NN / 256, 256>>>(coords);
    knn_scan_scatter<<<BB, NCELL>>>(coords);
    knn_main<<<BB * NN * 2 / 128, 128>>>();
    mlp2_kernel<<<(BB * NN) / 8, 256>>>(pf, coords, aw, out);
}

// round 7
// speedup vs baseline: 3.9504x; 1.3845x over previous
#include <cuda_runtime.h>
#include <cstdint>

#define BB   2
#define NN   8192
#define CIN  64
#define CCAT 67
#define KK   16
#define H1   32
#define H2   64
#define COUT 64

#define GRID 8            // 8x8x8 cells
#define NCELL (GRID*GRID*GRID)
#define CS   0.125f       // cell size

typedef unsigned long long u64;

__device__ int    g_knn[BB * NN * KK];
__device__ int    g_cnt[BB * NCELL];          // zero-initialized; scan resets it
__device__ int    g_start[BB * (NCELL + 1)];
__device__ float4 g_sorted[BB * NN];
__device__ float  g_W[COUT * 68];             // collapsed MLP matrix, col 67 = 0
__device__ float  g_C1[COUT];                 // 16 * B
__device__ float  g_C2[COUT];                 // sum(aggr_w) * B + aggr_b

__device__ __forceinline__ int cell_of(float x, float y, float z) {
    int ix = min(GRID - 1, max(0, (int)(x * (float)GRID)));
    int iy = min(GRID - 1, max(0, (int)(y * (float)GRID)));
    int iz = min(GRID - 1, max(0, (int)(z * (float)GRID)));
    return (iz * GRID + iy) * GRID + ix;
}

// ---------------------------------------------------------------------------
// Collapse the affine MLP:  W = w3*w2*w1,  B = w3*(w2*b1 + b2) + b3
// ---------------------------------------------------------------------------
__global__ __launch_bounds__(256) void precomp(
    const float* __restrict__ w1, const float* __restrict__ b1,
    const float* __restrict__ w2, const float* __restrict__ b2,
    const float* __restrict__ w3, const float* __restrict__ b3,
    const float* __restrict__ aggr_w, const float* __restrict__ aggr_b)
{
    __shared__ float s0[4192];       // w1(2144)+w2(2048); later reused for w3(4096)
    __shared__ float s21[64 * 67];   // w2*w1
    __shared__ float st[64];         // w2*b1 + b2
    __shared__ float s_sumU;
    float* sw1 = s0;
    float* sw2 = s0 + 2144;
    const int t = threadIdx.x;
    for (int i = t; i < 2144; i += 256) sw1[i] = w1[i];
    for (int i = t; i < 2048; i += 256) sw2[i] = w2[i];
    if (t == 0) {
        float s = 0.f;
        for (int k = 0; k < KK; k++) s += aggr_w[k];
        s_sumU = s;
    }
    __syncthreads();
    if (t < 64) {
        float acc = b2[t];
        for (int j = 0; j < 32; j++) acc = fmaf(sw2[t * 32 + j], b1[j], acc);
        st[t] = acc;
    }
    for (int i = t; i < 64 * 67; i += 256) {
        int o = i / 67, c = i % 67;
        float acc = 0.f;
        for (int j = 0; j < 32; j++) acc = fmaf(sw2[o * 32 + j], sw1[j * 67 + c], acc);
        s21[i] = acc;
    }
    __syncthreads();
    float* sw3 = s0;                 // overlay (w1/w2 dead)
    for (int i = t; i < 4096; i += 256) sw3[i] = w3[i];
    __syncthreads();
    for (int i = t; i < 64 * 68; i += 256) {
        int o = i / 68, c = i % 68;
        float acc = 0.f;
        if (c < 67)
            for (int j = 0; j < 64; j++) acc = fmaf(sw3[o * 64 + j], s21[j * 67 + c], acc);
        g_W[i] = acc;                // col 67 stays 0 (pad)
    }
    if (t < 64) {
        float B = b3[t];
        for (int j = 0; j < 64; j++) B = fmaf(sw3[t * 64 + j], st[j], B);
        g_C1[t] = 16.0f * B;
        g_C2[t] = fmaf(s_sumU, B, aggr_b[0]);
    }
}

// ---------------------------------------------------------------------------
__global__ void knn_bin(const float* __restrict__ coords) {
    int t = blockIdx.x * blockDim.x + threadIdx.x;
    int b = t >> 13, q = t & (NN - 1);
    const float* cp = coords + ((size_t)b * NN + q) * 3;
    int c = cell_of(cp[0], cp[1], cp[2]);
    atomicAdd(&g_cnt[b * NCELL + c], 1);
}

__global__ __launch_bounds__(NCELL) void knn_scan_scatter(const float* __restrict__ coords) {
    __shared__ int s[NCELL];
    __shared__ int cur[NCELL];
    const int b = blockIdx.x, t = threadIdx.x;
    const int my = g_cnt[b * NCELL + t];
    s[t] = my;
    __syncthreads();
    for (int off = 1; off < NCELL; off <<= 1) {
        int v = (t >= off) ? s[t - off] : 0;
        __syncthreads();
        s[t] += v;
        __syncthreads();
    }
    g_start[b * (NCELL + 1) + t + 1] = s[t];
    if (t == 0) g_start[b * (NCELL + 1)] = 0;
    cur[t] = s[t] - my;
    g_cnt[b * NCELL + t] = 0;      // reset for next replay
    __syncthreads();
    for (int q = t; q < NN; q += NCELL) {
        const float* cp = coords + ((size_t)b * NN + q) * 3;
        float x = cp[0], y = cp[1], z = cp[2];
        int c = cell_of(x, y, z);
        int pos = atomicAdd(&cur[c], 1);
        g_sorted[(size_t)b * NN + pos] = make_float4(x, y, z, __int_as_float(q));
    }
}

// ---------------------------------------------------------------------------
// Exact KNN: 4 threads per query (candidate slices mod 4), expanding
// Chebyshev rings. Ring termination uses a MERGED threshold (exact 16th of
// pairwise unions, min across pairs) so slicing does not delay termination.
// Final result = exact two-stage bitonic merge of the 4 sorted top-16 lists.
// Keys are (sortable(d)<<32)|idx = stable (d, idx) order (jax top_k ties).
// ---------------------------------------------------------------------------
__device__ __forceinline__ u64 u64min(u64 a, u64 b) { return a < b ? a : b; }
__device__ __forceinline__ u64 u64max(u64 a, u64 b) { return a < b ? b : a; }

__global__ __launch_bounds__(256) void knn_main() {
    const int tt = blockIdx.x * 256 + threadIdx.x;
    const int pt = tt >> 2;           // query point
    const int parity = tt & 3;        // candidate slice
    const int lane = threadIdx.x & 31;
    const unsigned gmask = 0xFu << (lane & 28);   // the 4 threads of this query
    const int b = pt >> 13, slot = pt & (NN - 1);
    const float4* sp = g_sorted + (size_t)b * NN;
    const float4 me = sp[slot];
    const float qx = me.x, qy = me.y, qz = me.z;
    const int   q  = __float_as_int(me.w);
    const float qsq = fmaf(qz, qz, fmaf(qy, qy, qx * qx));
    const int cx = min(GRID - 1, max(0, (int)(qx * (float)GRID)));
    const int cy = min(GRID - 1, max(0, (int)(qy * (float)GRID)));
    const int cz = min(GRID - 1, max(0, (int)(qz * (float)GRID)));

    u64 keys[KK];
#pragma unroll
    for (int j = 0; j < KK; j++) keys[j] = 0xFF80000000000000ull;  // +inf
    float thr = __int_as_float(0x7F800000);

    const int* st = g_start + b * (NCELL + 1);

#define SCAN_RANGE(PA, PB)                                                     \
    for (int p = (PA) + ((parity - (PA)) & 3); p < (PB); p += 4) {             \
        const float4 cd = sp[p];                                               \
        const float csq = fmaf(cd.z, cd.z, fmaf(cd.y, cd.y, cd.x * cd.x));     \
        const float dot = fmaf(qz, cd.z, fmaf(qy, cd.y, qx * cd.x));           \
        const float d = fmaf(-2.0f, dot, qsq + csq);                           \
        if (d < thr) {                                                         \
            unsigned s_ = __float_as_uint(d);                                  \
            s_ ^= (unsigned)((int)s_ >> 31) | 0x80000000u;                     \
            u64 k_ = ((u64)s_ << 32) | (unsigned)__float_as_int(cd.w);         \
            _Pragma("unroll")                                                  \
            for (int j = 0; j < KK; j++) {                                     \
                const u64 kj = keys[j];                                        \
                const bool cl = k_ < kj;                                       \
                keys[j] = cl ? k_ : kj;                                        \
                k_ = cl ? kj : k_;                                             \
            }                                                                  \
            const unsigned hs = (unsigned)(keys[KK - 1] >> 32);                \
            const unsigned ob = (hs & 0x80000000u) ? (hs ^ 0x80000000u) : ~hs; \
            thr = __uint_as_float(ob);                                         \
        }                                                                      \
    }

    for (int R = 0; R <= GRID - 1; ++R) {
        const int z0 = max(cz - R, 0), z1 = min(cz + R, GRID - 1);
        const int y0 = max(cy - R, 0), y1 = min(cy + R, GRID - 1);
        const int x0 = max(cx - R, 0), x1 = min(cx + R, GRID - 1);
        for (int z = z0; z <= z1; z++) {
            const int az = abs(z - cz);
            for (int y = y0; y <= y1; y++) {
                const int m2 = max(az, abs(y - cy));
                const int rowbase = (z * GRID + y) * GRID;
                if (m2 == R) {
                    const int pa = st[rowbase + x0];
                    const int pb = st[rowbase + x1 + 1];
                    SCAN_RANGE(pa, pb)
                } else {
                    const int xl = cx - R, xr = cx + R;
                    if (xl >= 0) {
                        const int pa = st[rowbase + xl];
                        const int pb = st[rowbase + xl + 1];
                        SCAN_RANGE(pa, pb)
                    }
                    if (xr <= GRID - 1) {
                        const int pa = st[rowbase + xr];
                        const int pb = st[rowbase + xr + 1];
                        SCAN_RANGE(pa, pb)
                    }
                }
            }
        }
        // merged termination threshold: exact 16th of pair union, min over pairs
        u64 t12 = 0;
#pragma unroll
        for (int i = 0; i < KK; i++) {
            const u64 pk = __shfl_xor_sync(gmask, keys[KK - 1 - i], 1);
            t12 = u64max(t12, u64min(keys[i], pk));
        }
        const u64 t_all = u64min(t12, __shfl_xor_sync(gmask, t12, 2));
        const unsigned hs = (unsigned)(t_all >> 32);
        const unsigned ob = (hs & 0x80000000u) ? (hs ^ 0x80000000u) : ~hs;
        const float mthr = __uint_as_float(ob);
        const float bound = (float)R * CS;
        if (mthr < bound * bound * 0.9999f) break;  // unscanned cells >= R*CS away
    }
#undef SCAN_RANGE

    // exact merge stage 1: partner xor 1
    u64 m[KK];
#pragma unroll
    for (int i = 0; i < KK; i++) {
        const u64 pk = __shfl_xor_sync(gmask, keys[KK - 1 - i], 1);
        m[i] = u64min(keys[i], pk);   // 16 smallest of pair, bitonic
    }
#pragma unroll
    for (int s = 8; s >= 1; s >>= 1) {
#pragma unroll
        for (int i = 0; i < KK; i++) {
            if ((i & s) == 0) {
                const u64 lo = u64min(m[i], m[i + s]);
                const u64 hi = u64max(m[i], m[i + s]);
                m[i] = lo; m[i + s] = hi;
            }
        }
    }
    // exact merge stage 2: partner xor 2
    u64 f[KK];
#pragma unroll
    for (int i = 0; i < KK; i++) {
        const u64 pk = __shfl_xor_sync(gmask, m[KK - 1 - i], 2);
        f[i] = u64min(m[i], pk);
    }
#pragma unroll
    for (int s = 8; s >= 1; s >>= 1) {
#pragma unroll
        for (int i = 0; i < KK; i++) {
            if ((i & s) == 0) {
                const u64 lo = u64min(f[i], f[i + s]);
                const u64 hi = u64max(f[i], f[i + s]);
                f[i] = lo; f[i + s] = hi;
            }
        }
    }
    if (parity == 0) {
        int* outp = g_knn + ((size_t)b * NN + q) * KK;
#pragma unroll
        for (int j = 0; j < KK; j++) outp[j] = (int)(f[j] & 0xFFFFFFFFu);
    }
}

// ---------------------------------------------------------------------------
// Fused gather + collapsed-affine evaluation:
//   out_sum = W*s1 + C1,  pool = max_k g_k[:64],  aggr = W*s2 + C2
// One warp per point; sums accumulate in registers during the gather.
// ---------------------------------------------------------------------------
__device__ __forceinline__ void F2(u64& d, u64 a, u64 b) {
    asm("fma.rn.f32x2 %0, %1, %2, %0;" : "+l"(d) : "l"(a), "l"(b));
}
__device__ __forceinline__ float HADD(u64 v) {
    return __uint_as_float((unsigned)v) + __uint_as_float((unsigned)(v >> 32));
}
#define LD4(p)  (*reinterpret_cast<const float4*>(p))
#define LDU2(p) (*reinterpret_cast<const ulonglong2*>(p))

__global__ __launch_bounds__(256) void mlp2_kernel(
    const float* __restrict__ pf, const float* __restrict__ coords,
    const float* __restrict__ aggr_w, float* __restrict__ out)
{
    __shared__ __align__(16) float s_W[COUT * 68];
    __shared__ float s_C1[COUT], s_C2[COUT], s_u[KK];
    __shared__ __align__(16) float s_s[8][2][68];

    const int tid  = threadIdx.x;
    const int lane = tid & 31;
    const int w    = tid >> 5;

    for (int i = tid; i < COUT * 68; i += 256) s_W[i] = g_W[i];
    if (tid < 64) s_C1[tid] = g_C1[tid];
    else if (tid < 128) s_C2[tid - 64] = g_C2[tid - 64];
    else if (tid < 144) s_u[tid - 128] = aggr_w[tid - 128];
    __syncthreads();

    const int gp = blockIdx.x * 8 + w;
    const int b  = gp >> 13;
    const float* pfb = pf + (size_t)b * NN * CIN;
    const float* cob = coords + (size_t)b * NN * 3;

    const int nk = g_knn[(size_t)gp * KK + (lane & 15)];
    const int cc = (lane & 15) * 4;

    float4 pool = make_float4(-3.4e38f, -3.4e38f, -3.4e38f, -3.4e38f);
    float4 a1 = make_float4(0.f, 0.f, 0.f, 0.f);
    float4 a2 = a1;
#pragma unroll
    for (int k2 = 0; k2 < KK; k2 += 2) {
        const int k = k2 + (lane >> 4);
        const int m = __shfl_sync(0xffffffffu, nk, k);
        const float u = s_u[k];
        const float4 v = LD4(pfb + (size_t)m * CIN + cc);
        pool.x = fmaxf(pool.x, v.x); pool.y = fmaxf(pool.y, v.y);
        pool.z = fmaxf(pool.z, v.z); pool.w = fmaxf(pool.w, v.w);
        a1.x += v.x; a1.y += v.y; a1.z += v.z; a1.w += v.w;
        a2.x = fmaf(u, v.x, a2.x); a2.y = fmaf(u, v.y, a2.y);
        a2.z = fmaf(u, v.z, a2.z); a2.w = fmaf(u, v.w, a2.w);
    }
    // combine the two k-halves (lane <-> lane+16)
    pool.x = fmaxf(pool.x, __shfl_xor_sync(0xffffffffu, pool.x, 16));
    pool.y = fmaxf(pool.y, __shfl_xor_sync(0xffffffffu, pool.y, 16));
    pool.z = fmaxf(pool.z, __shfl_xor_sync(0xffffffffu, pool.z, 16));
    pool.w = fmaxf(pool.w, __shfl_xor_sync(0xffffffffu, pool.w, 16));
    a1.x += __shfl_xor_sync(0xffffffffu, a1.x, 16);
    a1.y += __shfl_xor_sync(0xffffffffu, a1.y, 16);
    a1.z += __shfl_xor_sync(0xffffffffu, a1.z, 16);
    a1.w += __shfl_xor_sync(0xffffffffu, a1.w, 16);
    a2.x += __shfl_xor_sync(0xffffffffu, a2.x, 16);
    a2.y += __shfl_xor_sync(0xffffffffu, a2.y, 16);
    a2.z += __shfl_xor_sync(0xffffffffu, a2.z, 16);
    a2.w += __shfl_xor_sync(0xffffffffu, a2.w, 16);

    // relative-coord channel sums (channels 64..66)
    const int m0 = __shfl_sync(0xffffffffu, nk, 0);
    const float c0x = cob[(size_t)m0 * 3 + 0];
    const float c0y = cob[(size_t)m0 * 3 + 1];
    const float c0z = cob[(size_t)m0 * 3 + 2];
    float dx = 0.f, dy = 0.f, dz = 0.f, ex = 0.f, ey = 0.f, ez = 0.f;
    if (lane < KK) {
        const float* cp = cob + (size_t)nk * 3;
        dx = cp[0] - c0x; dy = cp[1] - c0y; dz = cp[2] - c0z;
        const float u = s_u[lane];
        ex = u * dx; ey = u * dy; ez = u * dz;
    }
#pragma unroll
    for (int s = 8; s >= 1; s >>= 1) {
        dx += __shfl_xor_sync(0xffffffffu, dx, s);
        dy += __shfl_xor_sync(0xffffffffu, dy, s);
        dz += __shfl_xor_sync(0xffffffffu, dz, s);
        ex += __shfl_xor_sync(0xffffffffu, ex, s);
        ey += __shfl_xor_sync(0xffffffffu, ey, s);
        ez += __shfl_xor_sync(0xffffffffu, ez, s);
    }

    if (lane < 16) {
        *reinterpret_cast<float4*>(&s_s[w][0][cc]) = a1;
        *reinterpret_cast<float4*>(&s_s[w][1][cc]) = a2;
    }
    if (lane == 0) {
        s_s[w][0][64] = dx; s_s[w][0][65] = dy; s_s[w][0][66] = dz; s_s[w][0][67] = 0.f;
        s_s[w][1][64] = ex; s_s[w][1][65] = ey; s_s[w][1][66] = ez; s_s[w][1][67] = 0.f;
    }
    __syncwarp();

    // two 64x67 matvecs: lane handles outputs (lane, lane+32) for s1 and s2
    u64 A1 = 0, B1 = 0, A2 = 0, B2 = 0;
#pragma unroll
    for (int c = 0; c < 68; c += 4) {
        const ulonglong2 wA = LDU2(s_W + lane * 68 + c);
        const ulonglong2 wB = LDU2(s_W + (lane + 32) * 68 + c);
        const ulonglong2 x1 = LDU2(&s_s[w][0][c]);
        const ulonglong2 x2 = LDU2(&s_s[w][1][c]);
        F2(A1, x1.x, wA.x); F2(A1, x1.y, wA.y);
        F2(B1, x1.x, wB.x); F2(B1, x1.y, wB.y);
        F2(A2, x2.x, wA.x); F2(A2, x2.y, wA.y);
        F2(B2, x2.x, wB.x); F2(B2, x2.y, wB.y);
    }

    float* op = out + (size_t)gp * 192;
    op[lane]        = HADD(A1) + s_C1[lane];
    op[32 + lane]   = HADD(B1) + s_C1[lane + 32];
    op[128 + lane]  = HADD(A2) + s_C2[lane];
    op[160 + lane]  = HADD(B2) + s_C2[lane + 32];
    if (lane < 16) *reinterpret_cast<float4*>(op + 64 + cc) = pool;
}

// ---------------------------------------------------------------------------
extern "C" void kernel_launch(void* const* d_in, const int* in_sizes, int n_in,
                              void* d_out, int out_size) {
    const float* pf     = (const float*)d_in[0];
    const float* coords = (const float*)d_in[1];
    const float* w1     = (const float*)d_in[2];
    const float* b1     = (const float*)d_in[3];
    const float* w2     = (const float*)d_in[4];
    const float* b2     = (const float*)d_in[5];
    const float* w3     = (const float*)d_in[6];
    const float* b3     = (const float*)d_in[7];
    const float* aw     = (const float*)d_in[8];
    const float* ab     = (const float*)d_in[9];
    float* out = (float*)d_out;

    precomp<<<1, 256>>>(w1, b1, w2, b2, w3, b3, aw, ab);
    knn_bin<<<BB * NN / 256, 256>>>(coords);
    knn_scan_scatter<<<BB, NCELL>>>(coords);
    knn_main<<<BB * NN * 4 / 256, 256>>>();
    mlp2_kernel<<<(BB * NN) / 8, 256>>>(pf, coords, aw, out);
}